// round 1
// baseline (speedup 1.0000x reference)
#include <cuda_runtime.h>
#include <math.h>

#define BB   2
#define SS   2048
#define DD   1024
#define HH   16
#define DKK  64
#define MTOT (BB*SS)   // 4096

// Scratch (static device allocations, allowed by the harness rules)
__device__ float g_Q [(size_t)BB*HH*SS*DKK];   // [B,H,S,dk]
__device__ float g_K [(size_t)BB*HH*SS*DKK];
__device__ float g_V [(size_t)BB*HH*SS*DKK];
__device__ float g_AO[(size_t)BB*SS*DD];       // [B,S,D]

// ---------------------------------------------------------------------------
// C[M,N] = A[M,K] @ W[N,K]^T + bias,  M=4096, N=K=1024.
// PERMUTE=1: scatter output to [B,H,S,dk] layout (for Q/K/V).
// 128x128 block tile, BK=16, 256 threads, 8x8 micro-tile.
// ---------------------------------------------------------------------------
template<int PERMUTE>
__global__ void __launch_bounds__(256, 2)
gemm_bias_kernel(const float* __restrict__ A, const float* __restrict__ W,
                 const float* __restrict__ bias, float* __restrict__ C)
{
    __shared__ float As[16][128];   // [k][m]
    __shared__ float Bs[16][128];   // [k][n]
    const int K = DD;
    const int tid = threadIdx.x;
    const int m0 = blockIdx.y * 128;
    const int n0 = blockIdx.x * 128;
    const int tx = tid & 15;
    const int ty = tid >> 4;

    float acc[8][8];
    #pragma unroll
    for (int i = 0; i < 8; ++i)
        #pragma unroll
        for (int j = 0; j < 8; ++j) acc[i][j] = 0.f;

    for (int k0 = 0; k0 < K; k0 += 16) {
        // load 128x16 tiles of A and W, transposed into smem
        #pragma unroll
        for (int it = 0; it < 2; ++it) {
            int idx = tid + it * 256;       // 0..511
            int row = idx >> 2;             // 0..127
            int c4  = (idx & 3) << 2;       // 0,4,8,12
            float4 va = *(const float4*)(A + (size_t)(m0 + row) * K + k0 + c4);
            As[c4+0][row] = va.x; As[c4+1][row] = va.y;
            As[c4+2][row] = va.z; As[c4+3][row] = va.w;
            float4 vb = *(const float4*)(W + (size_t)(n0 + row) * K + k0 + c4);
            Bs[c4+0][row] = vb.x; Bs[c4+1][row] = vb.y;
            Bs[c4+2][row] = vb.z; Bs[c4+3][row] = vb.w;
        }
        __syncthreads();

        #pragma unroll
        for (int kk = 0; kk < 16; ++kk) {
            float a[8], b[8];
            *(float4*)&a[0] = *(const float4*)&As[kk][ty*8];
            *(float4*)&a[4] = *(const float4*)&As[kk][ty*8 + 4];
            *(float4*)&b[0] = *(const float4*)&Bs[kk][tx*8];
            *(float4*)&b[4] = *(const float4*)&Bs[kk][tx*8 + 4];
            #pragma unroll
            for (int i = 0; i < 8; ++i)
                #pragma unroll
                for (int j = 0; j < 8; ++j)
                    acc[i][j] = fmaf(a[i], b[j], acc[i][j]);
        }
        __syncthreads();
    }

    #pragma unroll
    for (int i = 0; i < 8; ++i) {
        int m = m0 + ty*8 + i;
        #pragma unroll
        for (int j = 0; j < 8; ++j) {
            int n = n0 + tx*8 + j;
            float v = acc[i][j] + bias[n];
            if (PERMUTE) {
                int b = m >> 11;          // m / S
                int s = m & (SS - 1);
                int h = n >> 6;           // n / dk
                int d = n & 63;
                C[((((size_t)b*HH + h)*SS + s) << 6) + d] = v;
            } else {
                C[(size_t)m * DD + n] = v;
            }
        }
    }
}

// ---------------------------------------------------------------------------
// Flash attention, fp32. grid = (S/64, B*H), block = 256.
// 64 q-rows x 64 k-cols tiles, dk=64 resident. Online softmax via shfl.
// ---------------------------------------------------------------------------
__global__ void __launch_bounds__(256)
flash_attn_kernel()
{
    extern __shared__ float smem[];
    float* Qt = smem;                  // [64][65]  Q^T: [d][r], pre-scaled
    float* KP = smem + 64*65;          // [64][65]  K^T: [d][c], reused as P^T: [kc][r]
    float* Vs = smem + 2*64*65;        // [64][64]  V:   [kc][d]

    const int tid = threadIdx.x;
    const int tx = tid & 15;           // col-group
    const int ty = tid >> 4;           // row-group
    const int bh = blockIdx.y;         // 0..31
    const int q0 = blockIdx.x * 64;

    const float* Qb = g_Q + (size_t)bh * SS * DKK;
    const float* Kb = g_K + (size_t)bh * SS * DKK;
    const float* Vb = g_V + (size_t)bh * SS * DKK;

    // load Q tile transposed + pre-scaled by 1/sqrt(dk)=0.125
    #pragma unroll
    for (int it = 0; it < 4; ++it) {
        int idx = tid + it * 256;      // 0..1023
        int row = idx >> 4;            // 0..63
        int d4  = (idx & 15) << 2;     // 0..60 step 4
        float4 v = *(const float4*)(Qb + ((size_t)(q0 + row) << 6) + d4);
        Qt[(d4+0)*65 + row] = v.x * 0.125f;
        Qt[(d4+1)*65 + row] = v.y * 0.125f;
        Qt[(d4+2)*65 + row] = v.z * 0.125f;
        Qt[(d4+3)*65 + row] = v.w * 0.125f;
    }

    float m_i[4], l_i[4], o[4][4];
    #pragma unroll
    for (int i = 0; i < 4; ++i) {
        m_i[i] = -1e30f; l_i[i] = 0.f;
        #pragma unroll
        for (int j = 0; j < 4; ++j) o[i][j] = 0.f;
    }

    for (int k0 = 0; k0 < SS; k0 += 64) {
        __syncthreads();  // Qt ready (1st iter); KP/Vs free from prev PV read

        // load K (transposed) and V tiles
        #pragma unroll
        for (int it = 0; it < 4; ++it) {
            int idx = tid + it * 256;
            int row = idx >> 4;
            int d4  = (idx & 15) << 2;
            float4 kv = *(const float4*)(Kb + ((size_t)(k0 + row) << 6) + d4);
            KP[(d4+0)*65 + row] = kv.x;
            KP[(d4+1)*65 + row] = kv.y;
            KP[(d4+2)*65 + row] = kv.z;
            KP[(d4+3)*65 + row] = kv.w;
            float4 vv = *(const float4*)(Vb + ((size_t)(k0 + row) << 6) + d4);
            *(float4*)&Vs[row*64 + d4] = vv;
        }
        __syncthreads();

        // S = Q @ K^T  (reduce over d)
        float sv[4][4];
        #pragma unroll
        for (int i = 0; i < 4; ++i)
            #pragma unroll
            for (int j = 0; j < 4; ++j) sv[i][j] = 0.f;

        #pragma unroll 2
        for (int d = 0; d < 64; ++d) {
            float qa[4], kb[4];
            #pragma unroll
            for (int i = 0; i < 4; ++i) qa[i] = Qt[d*65 + ty*4 + i];
            #pragma unroll
            for (int j = 0; j < 4; ++j) kb[j] = KP[d*65 + tx*4 + j];
            #pragma unroll
            for (int i = 0; i < 4; ++i)
                #pragma unroll
                for (int j = 0; j < 4; ++j)
                    sv[i][j] = fmaf(qa[i], kb[j], sv[i][j]);
        }

        // online softmax (row reductions across the 16-lane tx group)
        #pragma unroll
        for (int i = 0; i < 4; ++i) {
            float mx = fmaxf(fmaxf(sv[i][0], sv[i][1]), fmaxf(sv[i][2], sv[i][3]));
            #pragma unroll
            for (int off = 8; off; off >>= 1)
                mx = fmaxf(mx, __shfl_xor_sync(0xffffffffu, mx, off));
            float mnew = fmaxf(m_i[i], mx);
            float corr = __expf(m_i[i] - mnew);
            float rs = 0.f;
            #pragma unroll
            for (int j = 0; j < 4; ++j) {
                float p = __expf(sv[i][j] - mnew);
                sv[i][j] = p; rs += p;
            }
            #pragma unroll
            for (int off = 8; off; off >>= 1)
                rs += __shfl_xor_sync(0xffffffffu, rs, off);
            l_i[i] = l_i[i] * corr + rs;
            m_i[i] = mnew;
            #pragma unroll
            for (int j = 0; j < 4; ++j) o[i][j] *= corr;
        }
        __syncthreads();  // everyone done reading KP as K^T

        // write P transposed into KP:  P^T[kc][r]
        #pragma unroll
        for (int i = 0; i < 4; ++i)
            #pragma unroll
            for (int j = 0; j < 4; ++j)
                KP[(tx*4 + j)*65 + ty*4 + i] = sv[i][j];
        __syncthreads();

        // O += P @ V  (reduce over kc)
        #pragma unroll 2
        for (int kc = 0; kc < 64; ++kc) {
            float pa[4], vb[4];
            #pragma unroll
            for (int i = 0; i < 4; ++i) pa[i] = KP[kc*65 + ty*4 + i];
            #pragma unroll
            for (int j = 0; j < 4; ++j) vb[j] = Vs[kc*64 + tx*4 + j];
            #pragma unroll
            for (int i = 0; i < 4; ++i)
                #pragma unroll
                for (int j = 0; j < 4; ++j)
                    o[i][j] = fmaf(pa[i], vb[j], o[i][j]);
        }
    }

    // normalize + write to [B,S,D]
    const int b = bh >> 4;
    const int h = bh & 15;
    #pragma unroll
    for (int i = 0; i < 4; ++i) {
        float inv = 1.0f / l_i[i];
        int s = q0 + ty*4 + i;
        float4 r;
        r.x = o[i][0] * inv; r.y = o[i][1] * inv;
        r.z = o[i][2] * inv; r.w = o[i][3] * inv;
        *(float4*)(g_AO + ((size_t)b*SS + s)*DD + h*64 + tx*4) = r;
    }
}

// ---------------------------------------------------------------------------
extern "C" void kernel_launch(void* const* d_in, const int* in_sizes, int n_in,
                              void* d_out, int out_size)
{
    const float* q  = (const float*)d_in[0];
    const float* k  = (const float*)d_in[1];
    const float* v  = (const float*)d_in[2];
    const float* Wq = (const float*)d_in[3];
    const float* bq = (const float*)d_in[4];
    const float* Wk = (const float*)d_in[5];
    const float* bk = (const float*)d_in[6];
    const float* Wv = (const float*)d_in[7];
    const float* bv = (const float*)d_in[8];
    const float* Wo = (const float*)d_in[9];
    const float* bo = (const float*)d_in[10];
    float* out = (float*)d_out;

    float *gq, *gk, *gv, *gao;
    cudaGetSymbolAddress((void**)&gq,  g_Q);
    cudaGetSymbolAddress((void**)&gk,  g_K);
    cudaGetSymbolAddress((void**)&gv,  g_V);
    cudaGetSymbolAddress((void**)&gao, g_AO);

    dim3 gblk(256);
    dim3 ggrid(DD/128, MTOT/128);   // (8, 32)

    gemm_bias_kernel<1><<<ggrid, gblk>>>(q, Wq, bq, gq);
    gemm_bias_kernel<1><<<ggrid, gblk>>>(k, Wk, bk, gk);
    gemm_bias_kernel<1><<<ggrid, gblk>>>(v, Wv, bv, gv);

    size_t smem_bytes = (size_t)(2*64*65 + 64*64) * sizeof(float);  // 49664
    cudaFuncSetAttribute(flash_attn_kernel,
                         cudaFuncAttributeMaxDynamicSharedMemorySize,
                         (int)smem_bytes);
    flash_attn_kernel<<<dim3(SS/64, BB*HH), 256, smem_bytes>>>();

    gemm_bias_kernel<0><<<ggrid, gblk>>>(gao, Wo, bo, out);
}

// round 3
// speedup vs baseline: 3.0806x; 3.0806x over previous
#include <cuda_runtime.h>
#include <cuda_bf16.h>
#include <cstdint>
#include <math.h>

#define BB   2
#define SS   2048
#define DD   1024
#define HH   16
#define MTOT (BB*SS)   // 4096

// Scratch (static device allocations, allowed by the harness rules)
__device__ float g_Q [(size_t)BB*HH*SS*64];   // [B,H,S,dk]
__device__ float g_K [(size_t)BB*HH*SS*64];
__device__ float g_V [(size_t)BB*HH*SS*64];
__device__ float g_AO[(size_t)BB*SS*DD];      // [B,S,D]

// ---------------------------------------------------------------------------
// helpers
// ---------------------------------------------------------------------------
__device__ __forceinline__ uint32_t smem_u32(const void* p) {
    uint32_t a;
    asm("{ .reg .u64 t; cvta.to.shared.u64 t, %1; cvt.u32.u64 %0, t; }"
        : "=r"(a) : "l"(p));
    return a;
}

__device__ __forceinline__ void ldsm4(uint32_t* r, uint32_t a) {
    asm volatile("ldmatrix.sync.aligned.m8n8.x4.shared.b16 {%0,%1,%2,%3}, [%4];"
                 : "=r"(r[0]), "=r"(r[1]), "=r"(r[2]), "=r"(r[3]) : "r"(a));
}
__device__ __forceinline__ void ldsm4t(uint32_t* r, uint32_t a) {
    asm volatile("ldmatrix.sync.aligned.m8n8.x4.trans.shared.b16 {%0,%1,%2,%3}, [%4];"
                 : "=r"(r[0]), "=r"(r[1]), "=r"(r[2]), "=r"(r[3]) : "r"(a));
}

__device__ __forceinline__ void mma_bf16(float* c, const uint32_t* a,
                                         uint32_t b0, uint32_t b1) {
    asm volatile("mma.sync.aligned.m16n8k16.row.col.f32.bf16.bf16.f32 "
                 "{%0,%1,%2,%3}, {%4,%5,%6,%7}, {%8,%9}, {%0,%1,%2,%3};"
                 : "+f"(c[0]), "+f"(c[1]), "+f"(c[2]), "+f"(c[3])
                 : "r"(a[0]), "r"(a[1]), "r"(a[2]), "r"(a[3]), "r"(b0), "r"(b1));
}

__device__ __forceinline__ float ex2f(float x) {
    float y;
    asm("ex2.approx.f32 %0, %1;" : "=f"(y) : "f"(x));
    return y;
}

// split fp32x4 into bf16 hi + bf16 lo, store 8B each
__device__ __forceinline__ void split4(float4 v, __nv_bfloat16* hp, __nv_bfloat16* lp) {
    __nv_bfloat162 h01 = __floats2bfloat162_rn(v.x, v.y);
    __nv_bfloat162 h23 = __floats2bfloat162_rn(v.z, v.w);
    float2 f01 = __bfloat1622float2(h01);
    float2 f23 = __bfloat1622float2(h23);
    __nv_bfloat162 l01 = __floats2bfloat162_rn(v.x - f01.x, v.y - f01.y);
    __nv_bfloat162 l23 = __floats2bfloat162_rn(v.z - f23.x, v.w - f23.y);
    uint2 uh = make_uint2(*(uint32_t*)&h01, *(uint32_t*)&h23);
    uint2 ul = make_uint2(*(uint32_t*)&l01, *(uint32_t*)&l23);
    *(uint2*)hp = uh;
    *(uint2*)lp = ul;
}

// ---------------------------------------------------------------------------
// GEMM: C[M=4096,N=1024] = A[M,K=1024] @ W[N,K]^T + bias   (bf16x3 mma.sync)
// 128x128 CTA tile, BK=32, 8 warps (2m x 4n), warp tile 64x32.
// PERMUTE=1: scatter to [B,H,S,dk].
// ---------------------------------------------------------------------------
#define GP 40   // padded row stride (bf16 elems), 80B: conflict-free ldmatrix

template<int PERMUTE>
__global__ void __launch_bounds__(256)
gemm_mma_kernel(const float* __restrict__ A, const float* __restrict__ W,
                const float* __restrict__ bias, float* __restrict__ C)
{
    __shared__ __align__(16) __nv_bfloat16 sAh[128*GP], sAl[128*GP];
    __shared__ __align__(16) __nv_bfloat16 sWh[128*GP], sWl[128*GP];

    const int tid  = threadIdx.x;
    const int lane = tid & 31;
    const int wid  = tid >> 5;
    const int wm = wid >> 2, wn = wid & 3;
    const int m0 = blockIdx.y * 128, n0 = blockIdx.x * 128;

    const uint32_t uAh = smem_u32(sAh), uAl = smem_u32(sAl);
    const uint32_t uWh = smem_u32(sWh), uWl = smem_u32(sWl);

    float acc[4][4][4];
    #pragma unroll
    for (int i = 0; i < 4; ++i)
        #pragma unroll
        for (int j = 0; j < 4; ++j)
            #pragma unroll
            for (int e = 0; e < 4; ++e) acc[i][j][e] = 0.f;

    for (int c = 0; c < 32; ++c) {
        __syncthreads();
        const int kg = c * 32;
        #pragma unroll
        for (int i = 0; i < 4; ++i) {
            int idx = tid + i * 256;
            int row = idx >> 3;
            int c4  = (idx & 7) << 2;
            int so  = row * GP + c4;
            float4 va = *(const float4*)(A + (size_t)(m0 + row) * DD + kg + c4);
            split4(va, sAh + so, sAl + so);
            float4 vw = *(const float4*)(W + (size_t)(n0 + row) * DD + kg + c4);
            split4(vw, sWh + so, sWl + so);
        }
        __syncthreads();

        #pragma unroll
        for (int ks = 0; ks < 2; ++ks) {
            uint32_t ah[4][4], al[4][4];
            #pragma unroll
            for (int mf = 0; mf < 4; ++mf) {
                int row = wm * 64 + mf * 16 + (lane & 15);
                uint32_t off = (uint32_t)(row * GP + ks * 16 + ((lane >> 4) << 3)) * 2;
                ldsm4(ah[mf], uAh + off);
                ldsm4(al[mf], uAl + off);
            }
            uint32_t bh[4][2], bl[4][2];
            #pragma unroll
            for (int nfp = 0; nfp < 2; ++nfp) {
                int row = wn * 32 + nfp * 16 + ((lane >> 4) << 3) + (lane & 7);
                uint32_t off = (uint32_t)(row * GP + ks * 16 + (((lane >> 3) & 1) << 3)) * 2;
                uint32_t r[4];
                ldsm4(r, uWh + off);
                bh[2*nfp][0] = r[0]; bh[2*nfp][1] = r[1];
                bh[2*nfp+1][0] = r[2]; bh[2*nfp+1][1] = r[3];
                ldsm4(r, uWl + off);
                bl[2*nfp][0] = r[0]; bl[2*nfp][1] = r[1];
                bl[2*nfp+1][0] = r[2]; bl[2*nfp+1][1] = r[3];
            }
            #pragma unroll
            for (int mf = 0; mf < 4; ++mf)
                #pragma unroll
                for (int nf = 0; nf < 4; ++nf) {
                    mma_bf16(acc[mf][nf], ah[mf], bh[nf][0], bh[nf][1]);
                    mma_bf16(acc[mf][nf], ah[mf], bl[nf][0], bl[nf][1]);
                    mma_bf16(acc[mf][nf], al[mf], bh[nf][0], bh[nf][1]);
                }
        }
    }

    // epilogue: c0,c1 -> (row l>>2, cols 2(l&3),+1); c2,c3 -> row+8
    #pragma unroll
    for (int mf = 0; mf < 4; ++mf)
        #pragma unroll
        for (int nf = 0; nf < 4; ++nf)
            #pragma unroll
            for (int h = 0; h < 2; ++h) {
                int m = m0 + wm * 64 + mf * 16 + (lane >> 2) + h * 8;
                int n = n0 + wn * 32 + nf * 8 + (lane & 3) * 2;
                float2 val;
                val.x = acc[mf][nf][2*h + 0] + bias[n];
                val.y = acc[mf][nf][2*h + 1] + bias[n + 1];
                if (PERMUTE) {
                    int b = m >> 11;
                    int s = m & (SS - 1);
                    int hh = n >> 6;
                    int d = n & 63;
                    *(float2*)(C + ((((size_t)b * HH + hh) * SS + s) << 6) + d) = val;
                } else {
                    *(float2*)(C + (size_t)m * DD + n) = val;
                }
            }
}

// ---------------------------------------------------------------------------
// Flash attention with bf16x3 mma.sync.
// grid = (S/128, B*H), 256 threads (8 warps, each owns 16 q rows).
// Tiles: 128 q x 128 kc, dk = 64.
// ---------------------------------------------------------------------------
#define QP 72   // padded row stride (bf16 elems), 144B

__global__ void __launch_bounds__(256)
flash_mma_kernel()
{
    extern __shared__ __nv_bfloat16 smb[];
    __nv_bfloat16* Qh = smb;
    __nv_bfloat16* Ql = Qh + 128 * QP;
    __nv_bfloat16* Kh = Ql + 128 * QP;
    __nv_bfloat16* Kl = Kh + 128 * QP;
    __nv_bfloat16* Vh = Kl + 128 * QP;
    __nv_bfloat16* Vl = Vh + 128 * QP;

    const int tid  = threadIdx.x;
    const int lane = tid & 31;
    const int wid  = tid >> 5;
    const int bh = blockIdx.y;
    const int q0 = blockIdx.x * 128;

    const uint32_t uQh = smem_u32(Qh), uQl = smem_u32(Ql);
    const uint32_t uKh = smem_u32(Kh), uKl = smem_u32(Kl);
    const uint32_t uVh = smem_u32(Vh), uVl = smem_u32(Vl);

    const float* Qg = g_Q + (size_t)bh * SS * 64;
    const float* Kg = g_K + (size_t)bh * SS * 64;
    const float* Vg = g_V + (size_t)bh * SS * 64;

    // scale = 1/sqrt(64) * log2(e), folded into Q so softmax uses ex2
    const float SCALE = 0.125f * 1.44269504088896340736f;

    // load Q tile (128 x 64), scaled + split
    #pragma unroll
    for (int i = 0; i < 8; ++i) {
        int idx = tid + i * 256;
        int row = idx >> 4;
        int c4  = (idx & 15) << 2;
        float4 v = *(const float4*)(Qg + ((size_t)(q0 + row) << 6) + c4);
        v.x *= SCALE; v.y *= SCALE; v.z *= SCALE; v.w *= SCALE;
        split4(v, Qh + row * QP + c4, Ql + row * QP + c4);
    }
    __syncthreads();

    // Q fragments into registers (m16k16 x 4 k-frags, hi+lo)
    uint32_t qh[4][4], ql[4][4];
    #pragma unroll
    for (int kf = 0; kf < 4; ++kf) {
        int row = wid * 16 + (lane & 15);
        uint32_t off = (uint32_t)(row * QP + kf * 16 + ((lane >> 4) << 3)) * 2;
        ldsm4(qh[kf], uQh + off);
        ldsm4(ql[kf], uQl + off);
    }

    float o[8][4];
    #pragma unroll
    for (int i = 0; i < 8; ++i)
        #pragma unroll
        for (int j = 0; j < 4; ++j) o[i][j] = 0.f;
    float mrow[2] = {-1e30f, -1e30f};
    float lrow[2] = {0.f, 0.f};

    for (int t = 0; t < 16; ++t) {
        __syncthreads();
        const int kc0 = t * 128;
        #pragma unroll
        for (int i = 0; i < 8; ++i) {
            int idx = tid + i * 256;
            int row = idx >> 4;
            int c4  = (idx & 15) << 2;
            float4 kv = *(const float4*)(Kg + ((size_t)(kc0 + row) << 6) + c4);
            split4(kv, Kh + row * QP + c4, Kl + row * QP + c4);
            float4 vv = *(const float4*)(Vg + ((size_t)(kc0 + row) << 6) + c4);
            split4(vv, Vh + row * QP + c4, Vl + row * QP + c4);
        }
        __syncthreads();

        // S = Q @ K^T : 16 n-frags (n = kc), k over d (4 frags)
        float s[16][4];
        #pragma unroll
        for (int nfp = 0; nfp < 8; ++nfp) {
            float s0[4] = {0.f, 0.f, 0.f, 0.f};
            float s1[4] = {0.f, 0.f, 0.f, 0.f};
            #pragma unroll
            for (int kf = 0; kf < 4; ++kf) {
                int row = nfp * 16 + ((lane >> 4) << 3) + (lane & 7);
                uint32_t off = (uint32_t)(row * QP + kf * 16 + (((lane >> 3) & 1) << 3)) * 2;
                uint32_t rh[4], rl[4];
                ldsm4(rh, uKh + off);
                ldsm4(rl, uKl + off);
                mma_bf16(s0, qh[kf], rh[0], rh[1]);
                mma_bf16(s0, qh[kf], rl[0], rl[1]);
                mma_bf16(s0, ql[kf], rh[0], rh[1]);
                mma_bf16(s1, qh[kf], rh[2], rh[3]);
                mma_bf16(s1, qh[kf], rl[2], rl[3]);
                mma_bf16(s1, ql[kf], rh[2], rh[3]);
            }
            #pragma unroll
            for (int e = 0; e < 4; ++e) { s[2*nfp][e] = s0[e]; s[2*nfp+1][e] = s1[e]; }
        }

        // online softmax (base-2 domain); rows: h=0 -> lane>>2, h=1 -> +8
        #pragma unroll
        for (int h = 0; h < 2; ++h) {
            float mx = -1e30f;
            #pragma unroll
            for (int nf = 0; nf < 16; ++nf)
                mx = fmaxf(mx, fmaxf(s[nf][2*h], s[nf][2*h + 1]));
            mx = fmaxf(mx, __shfl_xor_sync(0xffffffffu, mx, 1));
            mx = fmaxf(mx, __shfl_xor_sync(0xffffffffu, mx, 2));
            float mn = fmaxf(mrow[h], mx);
            float corr = ex2f(mrow[h] - mn);
            float rs = 0.f;
            #pragma unroll
            for (int nf = 0; nf < 16; ++nf) {
                float p0 = ex2f(s[nf][2*h]     - mn);
                float p1 = ex2f(s[nf][2*h + 1] - mn);
                s[nf][2*h] = p0; s[nf][2*h + 1] = p1;
                rs += p0 + p1;
            }
            rs += __shfl_xor_sync(0xffffffffu, rs, 1);
            rs += __shfl_xor_sync(0xffffffffu, rs, 2);
            lrow[h] = lrow[h] * corr + rs;
            mrow[h] = mn;
            #pragma unroll
            for (int nf = 0; nf < 8; ++nf) {
                o[nf][2*h] *= corr; o[nf][2*h + 1] *= corr;
            }
        }

        // pack P to bf16 hi/lo in registers (C-frag layout == A-frag layout)
        uint32_t p0h[16], p1h[16], p0l[16], p1l[16];
        #pragma unroll
        for (int nf = 0; nf < 16; ++nf) {
            __nv_bfloat162 h01 = __floats2bfloat162_rn(s[nf][0], s[nf][1]);
            __nv_bfloat162 h23 = __floats2bfloat162_rn(s[nf][2], s[nf][3]);
            float2 f01 = __bfloat1622float2(h01);
            float2 f23 = __bfloat1622float2(h23);
            __nv_bfloat162 l01 = __floats2bfloat162_rn(s[nf][0] - f01.x, s[nf][1] - f01.y);
            __nv_bfloat162 l23 = __floats2bfloat162_rn(s[nf][2] - f23.x, s[nf][3] - f23.y);
            p0h[nf] = *(uint32_t*)&h01; p1h[nf] = *(uint32_t*)&h23;
            p0l[nf] = *(uint32_t*)&l01; p1l[nf] = *(uint32_t*)&l23;
        }

        // O += P @ V : k over kc (8 frags), n over d (8 frags)
        #pragma unroll
        for (int kf = 0; kf < 8; ++kf) {
            uint32_t ah2[4] = { p0h[2*kf], p1h[2*kf], p0h[2*kf+1], p1h[2*kf+1] };
            uint32_t al2[4] = { p0l[2*kf], p1l[2*kf], p0l[2*kf+1], p1l[2*kf+1] };
            #pragma unroll
            for (int dn = 0; dn < 4; ++dn) {
                int row = kf * 16 + ((lane >> 3) & 1) * 8 + (lane & 7);
                int col = dn * 16 + (lane >> 4) * 8;
                uint32_t off = (uint32_t)(row * QP + col) * 2;
                uint32_t vh4[4], vl4[4];
                ldsm4t(vh4, uVh + off);
                ldsm4t(vl4, uVl + off);
                mma_bf16(o[2*dn],   ah2, vh4[0], vh4[1]);
                mma_bf16(o[2*dn],   ah2, vl4[0], vl4[1]);
                mma_bf16(o[2*dn],   al2, vh4[0], vh4[1]);
                mma_bf16(o[2*dn+1], ah2, vh4[2], vh4[3]);
                mma_bf16(o[2*dn+1], ah2, vl4[2], vl4[3]);
                mma_bf16(o[2*dn+1], al2, vh4[2], vh4[3]);
            }
        }
    }

    // epilogue
    const int b  = bh >> 4;
    const int hh = bh & 15;
    #pragma unroll
    for (int h = 0; h < 2; ++h) {
        float inv = 1.0f / lrow[h];
        int srow = q0 + wid * 16 + (lane >> 2) + h * 8;
        #pragma unroll
        for (int nf = 0; nf < 8; ++nf) {
            int d = nf * 8 + (lane & 3) * 2;
            float2 val;
            val.x = o[nf][2*h]     * inv;
            val.y = o[nf][2*h + 1] * inv;
            *(float2*)(g_AO + ((size_t)b * SS + srow) * DD + hh * 64 + d) = val;
        }
    }
}

#define ATTN_SMEM (6 * 128 * QP * 2)

// ---------------------------------------------------------------------------
extern "C" void kernel_launch(void* const* d_in, const int* in_sizes, int n_in,
                              void* d_out, int out_size)
{
    const float* q  = (const float*)d_in[0];
    const float* k  = (const float*)d_in[1];
    const float* v  = (const float*)d_in[2];
    const float* Wq = (const float*)d_in[3];
    const float* bq = (const float*)d_in[4];
    const float* Wk = (const float*)d_in[5];
    const float* bk = (const float*)d_in[6];
    const float* Wv = (const float*)d_in[7];
    const float* bv = (const float*)d_in[8];
    const float* Wo = (const float*)d_in[9];
    const float* bo = (const float*)d_in[10];
    float* out = (float*)d_out;

    float *gq, *gk, *gv, *gao;
    cudaGetSymbolAddress((void**)&gq,  g_Q);
    cudaGetSymbolAddress((void**)&gk,  g_K);
    cudaGetSymbolAddress((void**)&gv,  g_V);
    cudaGetSymbolAddress((void**)&gao, g_AO);

    dim3 gblk(256);
    dim3 ggrid(DD / 128, MTOT / 128);   // (8, 32)

    gemm_mma_kernel<1><<<ggrid, gblk>>>(q, Wq, bq, gq);
    gemm_mma_kernel<1><<<ggrid, gblk>>>(k, Wk, bk, gk);
    gemm_mma_kernel<1><<<ggrid, gblk>>>(v, Wv, bv, gv);

    cudaFuncSetAttribute(flash_mma_kernel,
                         cudaFuncAttributeMaxDynamicSharedMemorySize, ATTN_SMEM);
    flash_mma_kernel<<<dim3(SS / 128, BB * HH), 256, ATTN_SMEM>>>();

    gemm_mma_kernel<0><<<ggrid, gblk>>>(gao, Wo, bo, out);
}

// round 4
// speedup vs baseline: 3.4929x; 1.1338x over previous
#include <cuda_runtime.h>
#include <cuda_bf16.h>
#include <cstdint>
#include <stddef.h>

#define BB   2
#define SS   2048
#define DD   1024
#define HH   16
#define MTOT (BB*SS)            // 4096
#define NIN  ((size_t)MTOT*DD)  // 4194304
#define NW   ((size_t)DD*DD)    // 1048576

// ---------------------------------------------------------------------------
// Scratch: everything pre-split into bf16 hi/lo (static device alloc, ~128MB)
// ---------------------------------------------------------------------------
struct Scratch {
    __nv_bfloat16 aq_h[NIN], aq_l[NIN];   // split inputs (GEMM A operands)
    __nv_bfloat16 ak_h[NIN], ak_l[NIN];
    __nv_bfloat16 av_h[NIN], av_l[NIN];
    __nv_bfloat16 wq_h[NW],  wq_l[NW];    // split weights
    __nv_bfloat16 wk_h[NW],  wk_l[NW];
    __nv_bfloat16 wv_h[NW],  wv_l[NW];
    __nv_bfloat16 wo_h[NW],  wo_l[NW];
    __nv_bfloat16 Qh[NIN], Ql[NIN];       // projected, [B,H,S,64], Q pre-scaled
    __nv_bfloat16 Kh[NIN], Kl[NIN];
    __nv_bfloat16 Vh[NIN], Vl[NIN];
    __nv_bfloat16 AOh[NIN], AOl[NIN];     // attention out, [B,S,D], split
};
__device__ Scratch g_s;

// ---------------------------------------------------------------------------
// helpers
// ---------------------------------------------------------------------------
__device__ __forceinline__ uint32_t smem_u32(const void* p) {
    uint32_t a;
    asm("{ .reg .u64 t; cvta.to.shared.u64 t, %1; cvt.u32.u64 %0, t; }"
        : "=r"(a) : "l"(p));
    return a;
}
__device__ __forceinline__ void ldsm4(uint32_t* r, uint32_t a) {
    asm volatile("ldmatrix.sync.aligned.m8n8.x4.shared.b16 {%0,%1,%2,%3}, [%4];"
                 : "=r"(r[0]), "=r"(r[1]), "=r"(r[2]), "=r"(r[3]) : "r"(a));
}
__device__ __forceinline__ void ldsm4t(uint32_t* r, uint32_t a) {
    asm volatile("ldmatrix.sync.aligned.m8n8.x4.trans.shared.b16 {%0,%1,%2,%3}, [%4];"
                 : "=r"(r[0]), "=r"(r[1]), "=r"(r[2]), "=r"(r[3]) : "r"(a));
}
__device__ __forceinline__ void mma_bf16(float* c, const uint32_t* a,
                                         uint32_t b0, uint32_t b1) {
    asm volatile("mma.sync.aligned.m16n8k16.row.col.f32.bf16.bf16.f32 "
                 "{%0,%1,%2,%3}, {%4,%5,%6,%7}, {%8,%9}, {%0,%1,%2,%3};"
                 : "+f"(c[0]), "+f"(c[1]), "+f"(c[2]), "+f"(c[3])
                 : "r"(a[0]), "r"(a[1]), "r"(a[2]), "r"(a[3]), "r"(b0), "r"(b1));
}
__device__ __forceinline__ float ex2f(float x) {
    float y; asm("ex2.approx.f32 %0, %1;" : "=f"(y) : "f"(x)); return y;
}
__device__ __forceinline__ void cp16(uint32_t dst, const void* src) {
    asm volatile("cp.async.cg.shared.global [%0], [%1], 16;"
                 :: "r"(dst), "l"(src) : "memory");
}
#define CP_COMMIT() asm volatile("cp.async.commit_group;" ::: "memory")
#define CP_WAIT1()  asm volatile("cp.async.wait_group 1;" ::: "memory")
#define CP_WAIT0()  asm volatile("cp.async.wait_group 0;" ::: "memory")

// swizzled smem offset within a 128B-row tile region: row r, 16B-chunk cx
__device__ __forceinline__ uint32_t swz(int r, int cx) {
    return (uint32_t)(r * 128 + ((cx ^ (r & 7)) << 4));
}

// split fp32 pair -> bf16 hi/lo pair stores
__device__ __forceinline__ void split2_store(float x, float y,
                                             __nv_bfloat16* hp, __nv_bfloat16* lp) {
    __nv_bfloat162 H = __floats2bfloat162_rn(x, y);
    float2 F = __bfloat1622float2(H);
    __nv_bfloat162 L = __floats2bfloat162_rn(x - F.x, y - F.y);
    *(__nv_bfloat162*)hp = H;
    *(__nv_bfloat162*)lp = L;
}

// ---------------------------------------------------------------------------
// elementwise fp32 -> bf16 hi/lo split
// ---------------------------------------------------------------------------
__global__ void __launch_bounds__(256)
split_kernel(const float4* __restrict__ src, __nv_bfloat16* __restrict__ hi,
             __nv_bfloat16* __restrict__ lo)
{
    size_t i = (size_t)blockIdx.x * blockDim.x + threadIdx.x;
    float4 v = src[i];
    split2_store(v.x, v.y, hi + 4*i,     lo + 4*i);
    split2_store(v.z, v.w, hi + 4*i + 2, lo + 4*i + 2);
}

// ---------------------------------------------------------------------------
// GEMM: C[4096,1024] = A @ W^T + bias, bf16x3, pre-split inputs.
// 128x128 CTA tile, BK=64, 8 warps (2m x 4n), cp.async 2-stage pipeline.
// OUT_SPLIT=1: write bf16 hi/lo to [B,H,S,64] with scale. 0: fp32 [M,D].
// smem: 2 bufs x {Ah,Al,Wh,Wl} x 16KB = 131072 B dynamic.
// ---------------------------------------------------------------------------
#define GEMM_SMEM 131072

template<int OUT_SPLIT>
__global__ void __launch_bounds__(256, 1)
gemm_mma(const __nv_bfloat16* __restrict__ Ah, const __nv_bfloat16* __restrict__ Al,
         const __nv_bfloat16* __restrict__ Wh, const __nv_bfloat16* __restrict__ Wl,
         const float* __restrict__ bias, float* __restrict__ Cf,
         __nv_bfloat16* __restrict__ Ch, __nv_bfloat16* __restrict__ Cl,
         float oscale)
{
    extern __shared__ char smg[];
    const uint32_t sb = smem_u32(smg);
    const int tid = threadIdx.x, lane = tid & 31, wid = tid >> 5;
    const int wm = wid >> 2, wn = wid & 3;
    const int m0 = blockIdx.y * 128, n0 = blockIdx.x * 128;

    auto issue = [&](int c, int buf) {
        const int k0 = c * 64;
        #pragma unroll
        for (int i = 0; i < 16; ++i) {
            int idx = tid + i * 256;          // 0..4095
            int tn  = idx >> 10;              // 0:Ah 1:Al 2:Wh 3:Wl
            int w   = idx & 1023;
            int r   = w >> 3, cx = w & 7;
            const __nv_bfloat16* src;
            if      (tn == 0) src = Ah + (size_t)(m0 + r) * DD + k0 + cx * 8;
            else if (tn == 1) src = Al + (size_t)(m0 + r) * DD + k0 + cx * 8;
            else if (tn == 2) src = Wh + (size_t)(n0 + r) * DD + k0 + cx * 8;
            else              src = Wl + (size_t)(n0 + r) * DD + k0 + cx * 8;
            cp16(sb + (uint32_t)buf * 65536u + (uint32_t)tn * 16384u + swz(r, cx), src);
        }
        CP_COMMIT();
    };

    float acc[4][4][4];
    #pragma unroll
    for (int i = 0; i < 4; ++i)
        #pragma unroll
        for (int j = 0; j < 4; ++j)
            #pragma unroll
            for (int e = 0; e < 4; ++e) acc[i][j][e] = 0.f;

    issue(0, 0);
    for (int c = 0; c < 16; ++c) {
        if (c < 15) { issue(c + 1, (c + 1) & 1); CP_WAIT1(); }
        else        { CP_WAIT0(); }
        __syncthreads();

        const uint32_t base = sb + (uint32_t)(c & 1) * 65536u;
        #pragma unroll
        for (int ks = 0; ks < 4; ++ks) {
            uint32_t ahf[4][4], alf[4][4];
            #pragma unroll
            for (int mf = 0; mf < 4; ++mf) {
                int row = wm * 64 + mf * 16 + (lane & 15);
                int cx  = ks * 2 + (lane >> 4);
                uint32_t a = base + swz(row, cx);
                ldsm4(ahf[mf], a);
                ldsm4(alf[mf], a + 16384);
            }
            uint32_t bhf[4][2], blf[4][2];
            #pragma unroll
            for (int nfp = 0; nfp < 2; ++nfp) {
                int row = wn * 32 + nfp * 16 + ((lane >> 4) << 3) + (lane & 7);
                int cx  = ks * 2 + ((lane >> 3) & 1);
                uint32_t a = base + 32768 + swz(row, cx);
                uint32_t r[4];
                ldsm4(r, a);
                bhf[2*nfp][0] = r[0]; bhf[2*nfp][1] = r[1];
                bhf[2*nfp+1][0] = r[2]; bhf[2*nfp+1][1] = r[3];
                ldsm4(r, a + 16384);
                blf[2*nfp][0] = r[0]; blf[2*nfp][1] = r[1];
                blf[2*nfp+1][0] = r[2]; blf[2*nfp+1][1] = r[3];
            }
            #pragma unroll
            for (int mf = 0; mf < 4; ++mf)
                #pragma unroll
                for (int nf = 0; nf < 4; ++nf) {
                    mma_bf16(acc[mf][nf], ahf[mf], bhf[nf][0], bhf[nf][1]);
                    mma_bf16(acc[mf][nf], ahf[mf], blf[nf][0], blf[nf][1]);
                    mma_bf16(acc[mf][nf], alf[mf], bhf[nf][0], bhf[nf][1]);
                }
        }
        __syncthreads();
    }

    #pragma unroll
    for (int mf = 0; mf < 4; ++mf)
        #pragma unroll
        for (int nf = 0; nf < 4; ++nf)
            #pragma unroll
            for (int h = 0; h < 2; ++h) {
                int m = m0 + wm * 64 + mf * 16 + (lane >> 2) + h * 8;
                int n = n0 + wn * 32 + nf * 8 + (lane & 3) * 2;
                float2 bb = *(const float2*)(bias + n);
                float vx = acc[mf][nf][2*h + 0] + bb.x;
                float vy = acc[mf][nf][2*h + 1] + bb.y;
                if (OUT_SPLIT) {
                    vx *= oscale; vy *= oscale;
                    int b = m >> 11, s = m & (SS - 1);
                    int hh = n >> 6, d = n & 63;
                    size_t off = ((((size_t)b * HH + hh) * SS + s) << 6) + d;
                    split2_store(vx, vy, Ch + off, Cl + off);
                } else {
                    float2 val; val.x = vx; val.y = vy;
                    *(float2*)(Cf + (size_t)m * DD + n) = val;
                }
            }
}

// ---------------------------------------------------------------------------
// Flash attention, bf16x3, pre-split Q/K/V, cp.async 2-stage pipeline.
// grid (16, 32), 256 threads. q-tile 128, kc-tile 128, dk 64.
// smem: Qh/Ql 32KB + 2 bufs x {Kh,Kl,Vh,Vl} 128KB = 163840 B dynamic.
// ---------------------------------------------------------------------------
#define ATTN_SMEM 163840

__global__ void __launch_bounds__(256, 1)
flash_mma_kernel(const __nv_bfloat16* __restrict__ Qh, const __nv_bfloat16* __restrict__ Ql,
                 const __nv_bfloat16* __restrict__ Kh, const __nv_bfloat16* __restrict__ Kl,
                 const __nv_bfloat16* __restrict__ Vh, const __nv_bfloat16* __restrict__ Vl,
                 __nv_bfloat16* __restrict__ AOh, __nv_bfloat16* __restrict__ AOl)
{
    extern __shared__ char smf[];
    const uint32_t sb = smem_u32(smf);
    const int tid = threadIdx.x, lane = tid & 31, wid = tid >> 5;
    const int bh = blockIdx.y;
    const int q0 = blockIdx.x * 128;
    const size_t hbase = (size_t)bh * SS * 64;

    // issue Q (group 0)
    #pragma unroll
    for (int i = 0; i < 8; ++i) {
        int idx = tid + i * 256;          // 0..2047
        int tn  = idx >> 10;              // 0:Qh 1:Ql
        int w   = idx & 1023;
        int r   = w >> 3, cx = w & 7;
        const __nv_bfloat16* src = (tn ? Ql : Qh) + hbase + (size_t)(q0 + r) * 64 + cx * 8;
        cp16(sb + (uint32_t)tn * 16384u + swz(r, cx), src);
    }
    CP_COMMIT();

    auto issue_kv = [&](int t, int buf) {
        const int kc0 = t * 128;
        #pragma unroll
        for (int i = 0; i < 16; ++i) {
            int idx = tid + i * 256;      // 0..4095
            int tn  = idx >> 10;          // 0:Kh 1:Kl 2:Vh 3:Vl
            int w   = idx & 1023;
            int r   = w >> 3, cx = w & 7;
            const __nv_bfloat16* src;
            if      (tn == 0) src = Kh + hbase + (size_t)(kc0 + r) * 64 + cx * 8;
            else if (tn == 1) src = Kl + hbase + (size_t)(kc0 + r) * 64 + cx * 8;
            else if (tn == 2) src = Vh + hbase + (size_t)(kc0 + r) * 64 + cx * 8;
            else              src = Vl + hbase + (size_t)(kc0 + r) * 64 + cx * 8;
            cp16(sb + 32768u + (uint32_t)buf * 65536u + (uint32_t)tn * 16384u + swz(r, cx), src);
        }
        CP_COMMIT();
    };

    issue_kv(0, 0);
    CP_WAIT1();            // Q complete
    __syncthreads();

    // Q fragments (hi+lo) into registers
    uint32_t qh[4][4], ql[4][4];
    #pragma unroll
    for (int kf = 0; kf < 4; ++kf) {
        int row = wid * 16 + (lane & 15);
        int cx  = kf * 2 + (lane >> 4);
        uint32_t a = sb + swz(row, cx);
        ldsm4(qh[kf], a);
        ldsm4(ql[kf], a + 16384);
    }

    float o[8][4];
    #pragma unroll
    for (int i = 0; i < 8; ++i)
        #pragma unroll
        for (int j = 0; j < 4; ++j) o[i][j] = 0.f;
    float mrow[2] = {-1e30f, -1e30f};
    float lrow[2] = {0.f, 0.f};

    for (int t = 0; t < 16; ++t) {
        if (t < 15) { issue_kv(t + 1, (t + 1) & 1); CP_WAIT1(); }
        else        { CP_WAIT0(); }
        __syncthreads();

        const uint32_t base = sb + 32768u + (uint32_t)(t & 1) * 65536u;

        // S = Q @ K^T
        float s[16][4];
        #pragma unroll
        for (int nfp = 0; nfp < 8; ++nfp) {
            float s0[4] = {0.f, 0.f, 0.f, 0.f};
            float s1[4] = {0.f, 0.f, 0.f, 0.f};
            #pragma unroll
            for (int kf = 0; kf < 4; ++kf) {
                int row = nfp * 16 + ((lane >> 4) << 3) + (lane & 7);
                int cx  = kf * 2 + ((lane >> 3) & 1);
                uint32_t a = base + swz(row, cx);
                uint32_t rh[4], rl[4];
                ldsm4(rh, a);
                ldsm4(rl, a + 16384);
                mma_bf16(s0, qh[kf], rh[0], rh[1]);
                mma_bf16(s0, qh[kf], rl[0], rl[1]);
                mma_bf16(s0, ql[kf], rh[0], rh[1]);
                mma_bf16(s1, qh[kf], rh[2], rh[3]);
                mma_bf16(s1, qh[kf], rl[2], rl[3]);
                mma_bf16(s1, ql[kf], rh[2], rh[3]);
            }
            #pragma unroll
            for (int e = 0; e < 4; ++e) { s[2*nfp][e] = s0[e]; s[2*nfp+1][e] = s1[e]; }
        }

        // online softmax (base-2; scale folded into Q)
        #pragma unroll
        for (int h = 0; h < 2; ++h) {
            float mx = -1e30f;
            #pragma unroll
            for (int nf = 0; nf < 16; ++nf)
                mx = fmaxf(mx, fmaxf(s[nf][2*h], s[nf][2*h + 1]));
            mx = fmaxf(mx, __shfl_xor_sync(0xffffffffu, mx, 1));
            mx = fmaxf(mx, __shfl_xor_sync(0xffffffffu, mx, 2));
            float mn = fmaxf(mrow[h], mx);
            float corr = ex2f(mrow[h] - mn);
            float rs = 0.f;
            #pragma unroll
            for (int nf = 0; nf < 16; ++nf) {
                float p0 = ex2f(s[nf][2*h]     - mn);
                float p1 = ex2f(s[nf][2*h + 1] - mn);
                s[nf][2*h] = p0; s[nf][2*h + 1] = p1;
                rs += p0 + p1;
            }
            rs += __shfl_xor_sync(0xffffffffu, rs, 1);
            rs += __shfl_xor_sync(0xffffffffu, rs, 2);
            lrow[h] = lrow[h] * corr + rs;
            mrow[h] = mn;
            #pragma unroll
            for (int nf = 0; nf < 8; ++nf) {
                o[nf][2*h] *= corr; o[nf][2*h + 1] *= corr;
            }
        }

        // O += P @ V  (pack P per-kf, fused)
        #pragma unroll
        for (int kf = 0; kf < 8; ++kf) {
            uint32_t ah2[4], al2[4];
            #pragma unroll
            for (int e = 0; e < 2; ++e) {
                const float* sp = s[2*kf + e];
                __nv_bfloat162 h01 = __floats2bfloat162_rn(sp[0], sp[1]);
                __nv_bfloat162 h23 = __floats2bfloat162_rn(sp[2], sp[3]);
                float2 f01 = __bfloat1622float2(h01);
                float2 f23 = __bfloat1622float2(h23);
                __nv_bfloat162 l01 = __floats2bfloat162_rn(sp[0] - f01.x, sp[1] - f01.y);
                __nv_bfloat162 l23 = __floats2bfloat162_rn(sp[2] - f23.x, sp[3] - f23.y);
                ah2[2*e + 0] = *(uint32_t*)&h01; ah2[2*e + 1] = *(uint32_t*)&h23;
                al2[2*e + 0] = *(uint32_t*)&l01; al2[2*e + 1] = *(uint32_t*)&l23;
            }
            #pragma unroll
            for (int dn = 0; dn < 4; ++dn) {
                int row = kf * 16 + ((lane >> 3) & 1) * 8 + (lane & 7);
                int cx  = dn * 2 + (lane >> 4);
                uint32_t a = base + 32768 + swz(row, cx);
                uint32_t vh4[4], vl4[4];
                ldsm4t(vh4, a);
                ldsm4t(vl4, a + 16384);
                mma_bf16(o[2*dn],   ah2, vh4[0], vh4[1]);
                mma_bf16(o[2*dn],   ah2, vl4[0], vl4[1]);
                mma_bf16(o[2*dn],   al2, vh4[0], vh4[1]);
                mma_bf16(o[2*dn+1], ah2, vh4[2], vh4[3]);
                mma_bf16(o[2*dn+1], ah2, vl4[2], vl4[3]);
                mma_bf16(o[2*dn+1], al2, vh4[2], vh4[3]);
            }
        }
        __syncthreads();
    }

    // epilogue: normalize, split, store to [B,S,D]
    const int b  = bh >> 4;
    const int hh = bh & 15;
    #pragma unroll
    for (int h = 0; h < 2; ++h) {
        float inv = 1.0f / lrow[h];
        int srow = q0 + wid * 16 + (lane >> 2) + h * 8;
        #pragma unroll
        for (int nf = 0; nf < 8; ++nf) {
            int d = nf * 8 + (lane & 3) * 2;
            size_t off = ((size_t)b * SS + srow) * DD + hh * 64 + d;
            split2_store(o[nf][2*h] * inv, o[nf][2*h + 1] * inv, AOh + off, AOl + off);
        }
    }
}

// ---------------------------------------------------------------------------
extern "C" void kernel_launch(void* const* d_in, const int* in_sizes, int n_in,
                              void* d_out, int out_size)
{
    const float* q  = (const float*)d_in[0];
    const float* k  = (const float*)d_in[1];
    const float* v  = (const float*)d_in[2];
    const float* Wq = (const float*)d_in[3];
    const float* bq = (const float*)d_in[4];
    const float* Wk = (const float*)d_in[5];
    const float* bk = (const float*)d_in[6];
    const float* Wv = (const float*)d_in[7];
    const float* bv = (const float*)d_in[8];
    const float* Wo = (const float*)d_in[9];
    const float* bo = (const float*)d_in[10];
    float* out = (float*)d_out;

    Scratch* S;
    cudaGetSymbolAddress((void**)&S, g_s);
    // member "access" below is pointer arithmetic only (device pointer + offset)

    const float QSCALE = 0.125f * 1.44269504088896340736f;

    // split inputs + weights
    split_kernel<<<NIN/4/256, 256>>>((const float4*)q, S->aq_h, S->aq_l);
    split_kernel<<<NIN/4/256, 256>>>((const float4*)k, S->ak_h, S->ak_l);
    split_kernel<<<NIN/4/256, 256>>>((const float4*)v, S->av_h, S->av_l);
    split_kernel<<<NW/4/256, 256>>>((const float4*)Wq, S->wq_h, S->wq_l);
    split_kernel<<<NW/4/256, 256>>>((const float4*)Wk, S->wk_h, S->wk_l);
    split_kernel<<<NW/4/256, 256>>>((const float4*)Wv, S->wv_h, S->wv_l);
    split_kernel<<<NW/4/256, 256>>>((const float4*)Wo, S->wo_h, S->wo_l);

    cudaFuncSetAttribute(gemm_mma<1>, cudaFuncAttributeMaxDynamicSharedMemorySize, GEMM_SMEM);
    cudaFuncSetAttribute(gemm_mma<0>, cudaFuncAttributeMaxDynamicSharedMemorySize, GEMM_SMEM);
    cudaFuncSetAttribute(flash_mma_kernel, cudaFuncAttributeMaxDynamicSharedMemorySize, ATTN_SMEM);

    dim3 gblk(256);
    dim3 ggrid(DD / 128, MTOT / 128);   // (8, 32)

    gemm_mma<1><<<ggrid, gblk, GEMM_SMEM>>>(S->aq_h, S->aq_l, S->wq_h, S->wq_l,
                                            bq, nullptr, S->Qh, S->Ql, QSCALE);
    gemm_mma<1><<<ggrid, gblk, GEMM_SMEM>>>(S->ak_h, S->ak_l, S->wk_h, S->wk_l,
                                            bk, nullptr, S->Kh, S->Kl, 1.0f);
    gemm_mma<1><<<ggrid, gblk, GEMM_SMEM>>>(S->av_h, S->av_l, S->wv_h, S->wv_l,
                                            bv, nullptr, S->Vh, S->Vl, 1.0f);

    flash_mma_kernel<<<dim3(SS / 128, BB * HH), 256, ATTN_SMEM>>>(
        S->Qh, S->Ql, S->Kh, S->Kl, S->Vh, S->Vl, S->AOh, S->AOl);

    gemm_mma<0><<<ggrid, gblk, GEMM_SMEM>>>(S->AOh, S->AOl, S->wo_h, S->wo_l,
                                            bo, out, nullptr, nullptr, 1.0f);
}

// round 5
// speedup vs baseline: 3.5315x; 1.0111x over previous
#include <cuda_runtime.h>
#include <cuda_bf16.h>
#include <cstdint>
#include <stddef.h>

#define BB   2
#define SS   2048
#define DD   1024
#define HH   16
#define MTOT (BB*SS)            // 4096
#define NIN  ((size_t)MTOT*DD)  // 4194304
#define NW   ((size_t)DD*DD)    // 1048576

// ---------------------------------------------------------------------------
// Scratch: everything pre-split into bf16 hi/lo (static device alloc)
// ---------------------------------------------------------------------------
struct Scratch {
    __nv_bfloat16 aq_h[NIN], aq_l[NIN];
    __nv_bfloat16 ak_h[NIN], ak_l[NIN];
    __nv_bfloat16 av_h[NIN], av_l[NIN];
    __nv_bfloat16 wq_h[NW],  wq_l[NW];
    __nv_bfloat16 wk_h[NW],  wk_l[NW];
    __nv_bfloat16 wv_h[NW],  wv_l[NW];
    __nv_bfloat16 wo_h[NW],  wo_l[NW];
    __nv_bfloat16 Qh[NIN], Ql[NIN];       // [B,H,S,64], Q pre-scaled
    __nv_bfloat16 Kh[NIN], Kl[NIN];
    __nv_bfloat16 Vh[NIN], Vl[NIN];
    __nv_bfloat16 AOh[NIN], AOl[NIN];     // [B,S,D]
};
__device__ Scratch g_s;

// ---------------------------------------------------------------------------
// helpers
// ---------------------------------------------------------------------------
__device__ __forceinline__ uint32_t smem_u32(const void* p) {
    uint32_t a;
    asm("{ .reg .u64 t; cvta.to.shared.u64 t, %1; cvt.u32.u64 %0, t; }"
        : "=r"(a) : "l"(p));
    return a;
}
__device__ __forceinline__ void ldsm4(uint32_t* r, uint32_t a) {
    asm volatile("ldmatrix.sync.aligned.m8n8.x4.shared.b16 {%0,%1,%2,%3}, [%4];"
                 : "=r"(r[0]), "=r"(r[1]), "=r"(r[2]), "=r"(r[3]) : "r"(a));
}
__device__ __forceinline__ void ldsm4t(uint32_t* r, uint32_t a) {
    asm volatile("ldmatrix.sync.aligned.m8n8.x4.trans.shared.b16 {%0,%1,%2,%3}, [%4];"
                 : "=r"(r[0]), "=r"(r[1]), "=r"(r[2]), "=r"(r[3]) : "r"(a));
}
__device__ __forceinline__ void mma_bf16(float* c, const uint32_t* a,
                                         uint32_t b0, uint32_t b1) {
    asm volatile("mma.sync.aligned.m16n8k16.row.col.f32.bf16.bf16.f32 "
                 "{%0,%1,%2,%3}, {%4,%5,%6,%7}, {%8,%9}, {%0,%1,%2,%3};"
                 : "+f"(c[0]), "+f"(c[1]), "+f"(c[2]), "+f"(c[3])
                 : "r"(a[0]), "r"(a[1]), "r"(a[2]), "r"(a[3]), "r"(b0), "r"(b1));
}
__device__ __forceinline__ float ex2f(float x) {
    float y; asm("ex2.approx.f32 %0, %1;" : "=f"(y) : "f"(x)); return y;
}
__device__ __forceinline__ void cp16(uint32_t dst, const void* src) {
    asm volatile("cp.async.cg.shared.global [%0], [%1], 16;"
                 :: "r"(dst), "l"(src) : "memory");
}
#define CP_COMMIT() asm volatile("cp.async.commit_group;" ::: "memory")
#define CP_WAIT0()  asm volatile("cp.async.wait_group 0;" ::: "memory")
#define CP_WAIT1()  asm volatile("cp.async.wait_group 1;" ::: "memory")

// swizzled offset within a tile whose rows are 128B: row r, 16B-chunk cx
__device__ __forceinline__ uint32_t swz(int r, int cx) {
    return (uint32_t)(r * 128 + ((cx ^ (r & 7)) << 4));
}

__device__ __forceinline__ void split2_store(float x, float y,
                                             __nv_bfloat16* hp, __nv_bfloat16* lp) {
    __nv_bfloat162 H = __floats2bfloat162_rn(x, y);
    float2 F = __bfloat1622float2(H);
    __nv_bfloat162 L = __floats2bfloat162_rn(x - F.x, y - F.y);
    *(__nv_bfloat162*)hp = H;
    *(__nv_bfloat162*)lp = L;
}

// ---------------------------------------------------------------------------
// elementwise fp32 -> bf16 hi/lo split
// ---------------------------------------------------------------------------
__global__ void __launch_bounds__(256)
split_kernel(const float4* __restrict__ src, __nv_bfloat16* __restrict__ hi,
             __nv_bfloat16* __restrict__ lo)
{
    size_t i = (size_t)blockIdx.x * blockDim.x + threadIdx.x;
    float4 v = src[i];
    split2_store(v.x, v.y, hi + 4*i,     lo + 4*i);
    split2_store(v.z, v.w, hi + 4*i + 2, lo + 4*i + 2);
}

// ---------------------------------------------------------------------------
// GEMM body: C[4096,1024] = A @ W^T + bias, bf16x3.
// CTA tile 128(M) x 256(N), BK=64, 8 warps (2m x 4n), warp tile 64x64.
// 2-stage cp.async. smem/stage: Ah 16K | Al 16K | Wh 32K | Wl 32K = 96K.
// ---------------------------------------------------------------------------
#define GEMM_SMEM (2*98304)

template<int OUT_SPLIT>
__device__ __noinline__ void gemm_body(
    const __nv_bfloat16* __restrict__ Ah, const __nv_bfloat16* __restrict__ Al,
    const __nv_bfloat16* __restrict__ Wh, const __nv_bfloat16* __restrict__ Wl,
    const float* __restrict__ bias, float* __restrict__ Cf,
    __nv_bfloat16* __restrict__ Ch, __nv_bfloat16* __restrict__ Cl,
    float oscale, char* smg)
{
    const uint32_t sb = smem_u32(smg);
    const int tid = threadIdx.x, lane = tid & 31, wid = tid >> 5;
    const int wm = wid >> 2, wn = wid & 3;
    const int m0 = blockIdx.y * 128, n0 = blockIdx.x * 256;

    auto issue = [&](int c, int stage) {
        const int k0 = c * 64;
        const uint32_t base = sb + (uint32_t)stage * 98304u;
        #pragma unroll
        for (int i = 0; i < 24; ++i) {
            int idx = tid + i * 256;          // 0..6143
            const __nv_bfloat16* src;
            uint32_t roff;
            int w;
            if (idx < 2048) {                 // A hi/lo: 128 rows each
                int tn = idx >> 10; w = idx & 1023;
                int r = w >> 3;
                src = (tn ? Al : Ah) + (size_t)(m0 + r) * DD + k0 + (w & 7) * 8;
                roff = (uint32_t)tn * 16384u;
            } else {                          // W hi/lo: 256 rows each
                int j = idx - 2048;
                int tn = j >> 11; w = j & 2047;
                int r = w >> 3;
                src = (tn ? Wl : Wh) + (size_t)(n0 + r) * DD + k0 + (w & 7) * 8;
                roff = 32768u + (uint32_t)tn * 32768u;
            }
            cp16(base + roff + swz(w >> 3, w & 7), src);
        }
        CP_COMMIT();
    };

    float acc[4][8][4];
    #pragma unroll
    for (int i = 0; i < 4; ++i)
        #pragma unroll
        for (int j = 0; j < 8; ++j)
            #pragma unroll
            for (int e = 0; e < 4; ++e) acc[i][j][e] = 0.f;

    issue(0, 0);
    for (int c = 0; c < 16; ++c) {
        if (c < 15) { issue(c + 1, (c + 1) & 1); CP_WAIT1(); }
        else        { CP_WAIT0(); }
        __syncthreads();

        const uint32_t base = sb + (uint32_t)(c & 1) * 98304u;
        #pragma unroll
        for (int ks = 0; ks < 4; ++ks) {
            uint32_t ahf[4][4], alf[4][4];
            #pragma unroll
            for (int mf = 0; mf < 4; ++mf) {
                int row = wm * 64 + mf * 16 + (lane & 15);
                int cx  = ks * 2 + (lane >> 4);
                uint32_t a = base + swz(row, cx);
                ldsm4(ahf[mf], a);
                ldsm4(alf[mf], a + 16384);
            }
            uint32_t bhf[8][2], blf[8][2];
            #pragma unroll
            for (int nfp = 0; nfp < 4; ++nfp) {
                int row = wn * 64 + nfp * 16 + ((lane >> 4) << 3) + (lane & 7);
                int cx  = ks * 2 + ((lane >> 3) & 1);
                uint32_t a = base + 32768 + swz(row, cx);
                uint32_t r[4];
                ldsm4(r, a);
                bhf[2*nfp][0] = r[0]; bhf[2*nfp][1] = r[1];
                bhf[2*nfp+1][0] = r[2]; bhf[2*nfp+1][1] = r[3];
                ldsm4(r, a + 32768);
                blf[2*nfp][0] = r[0]; blf[2*nfp][1] = r[1];
                blf[2*nfp+1][0] = r[2]; blf[2*nfp+1][1] = r[3];
            }
            #pragma unroll
            for (int mf = 0; mf < 4; ++mf)
                #pragma unroll
                for (int nf = 0; nf < 8; ++nf) {
                    mma_bf16(acc[mf][nf], ahf[mf], bhf[nf][0], bhf[nf][1]);
                    mma_bf16(acc[mf][nf], ahf[mf], blf[nf][0], blf[nf][1]);
                    mma_bf16(acc[mf][nf], alf[mf], bhf[nf][0], bhf[nf][1]);
                }
        }
        __syncthreads();
    }

    #pragma unroll
    for (int mf = 0; mf < 4; ++mf)
        #pragma unroll
        for (int nf = 0; nf < 8; ++nf)
            #pragma unroll
            for (int h = 0; h < 2; ++h) {
                int m = m0 + wm * 64 + mf * 16 + (lane >> 2) + h * 8;
                int n = n0 + wn * 64 + nf * 8 + (lane & 3) * 2;
                float2 bb = *(const float2*)(bias + n);
                float vx = acc[mf][nf][2*h + 0] + bb.x;
                float vy = acc[mf][nf][2*h + 1] + bb.y;
                if (OUT_SPLIT) {
                    vx *= oscale; vy *= oscale;
                    int b = m >> 11, s = m & (SS - 1);
                    int hh = n >> 6, d = n & 63;
                    size_t off = ((((size_t)b * HH + hh) * SS + s) << 6) + d;
                    split2_store(vx, vy, Ch + off, Cl + off);
                } else {
                    float2 val; val.x = vx; val.y = vy;
                    *(float2*)(Cf + (size_t)m * DD + n) = val;
                }
            }
}

// fused Q/K/V projections: blockIdx.z selects the GEMM
__global__ void __launch_bounds__(256, 1)
gemm_qkv(const float* __restrict__ bq, const float* __restrict__ bk,
         const float* __restrict__ bv)
{
    extern __shared__ char smg[];
    const float QSCALE = 0.125f * 1.44269504088896340736f;
    int z = blockIdx.z;
    if (z == 0)
        gemm_body<1>(g_s.aq_h, g_s.aq_l, g_s.wq_h, g_s.wq_l, bq,
                     nullptr, g_s.Qh, g_s.Ql, QSCALE, smg);
    else if (z == 1)
        gemm_body<1>(g_s.ak_h, g_s.ak_l, g_s.wk_h, g_s.wk_l, bk,
                     nullptr, g_s.Kh, g_s.Kl, 1.0f, smg);
    else
        gemm_body<1>(g_s.av_h, g_s.av_l, g_s.wv_h, g_s.wv_l, bv,
                     nullptr, g_s.Vh, g_s.Vl, 1.0f, smg);
}

__global__ void __launch_bounds__(256, 1)
gemm_o(const float* __restrict__ bo, float* __restrict__ out)
{
    extern __shared__ char smg[];
    gemm_body<0>(g_s.AOh, g_s.AOl, g_s.wo_h, g_s.wo_l, bo,
                 out, nullptr, nullptr, 1.0f, smg);
}

// ---------------------------------------------------------------------------
// Flash attention, bf16x3, 3-stage cp.async pipeline, 1 sync per tile.
// grid (16, 32), 256 threads. q-tile 128, kc-tile 128, dk 64.
// smem: Qh/Ql 32KB + 3 stages x {Kh,Kl,Vh,Vl} 64KB = 229376 B.
// ---------------------------------------------------------------------------
#define ATTN_SMEM (32768 + 3*65536)

__global__ void __launch_bounds__(256, 1)
flash_mma_kernel()
{
    extern __shared__ char smf[];
    const uint32_t sb = smem_u32(smf);
    const int tid = threadIdx.x, lane = tid & 31, wid = tid >> 5;
    const int bh = blockIdx.y;
    const int q0 = blockIdx.x * 128;
    const size_t hbase = (size_t)bh * SS * 64;

    const __nv_bfloat16* Qhp = g_s.Qh + hbase;
    const __nv_bfloat16* Qlp = g_s.Ql + hbase;
    const __nv_bfloat16* Khp = g_s.Kh + hbase;
    const __nv_bfloat16* Klp = g_s.Kl + hbase;
    const __nv_bfloat16* Vhp = g_s.Vh + hbase;
    const __nv_bfloat16* Vlp = g_s.Vl + hbase;

    auto issue_kv = [&](int t, int stage) {
        const int kc0 = t * 128;
        const uint32_t base = sb + 32768u + (uint32_t)stage * 65536u;
        #pragma unroll
        for (int i = 0; i < 16; ++i) {
            int idx = tid + i * 256;      // 0..4095
            int tn  = idx >> 10;          // 0:Kh 1:Kl 2:Vh 3:Vl
            int w   = idx & 1023;
            int r   = w >> 3, cx = w & 7;
            const __nv_bfloat16* src;
            if      (tn == 0) src = Khp + (size_t)(kc0 + r) * 64 + cx * 8;
            else if (tn == 1) src = Klp + (size_t)(kc0 + r) * 64 + cx * 8;
            else if (tn == 2) src = Vhp + (size_t)(kc0 + r) * 64 + cx * 8;
            else              src = Vlp + (size_t)(kc0 + r) * 64 + cx * 8;
            cp16(base + (uint32_t)tn * 16384u + swz(r, cx), src);
        }
        CP_COMMIT();
    };

    // G0 = Q + kv0, G1 = kv1
    #pragma unroll
    for (int i = 0; i < 8; ++i) {
        int idx = tid + i * 256;          // 0..2047
        int tn  = idx >> 10;              // 0:Qh 1:Ql
        int w   = idx & 1023;
        int r   = w >> 3, cx = w & 7;
        const __nv_bfloat16* src = (tn ? Qlp : Qhp) + (size_t)(q0 + r) * 64 + cx * 8;
        cp16(sb + (uint32_t)tn * 16384u + swz(r, cx), src);
    }
    {
        const int kc0 = 0;
        const uint32_t base = sb + 32768u;
        #pragma unroll
        for (int i = 0; i < 16; ++i) {
            int idx = tid + i * 256;
            int tn  = idx >> 10;
            int w   = idx & 1023;
            int r   = w >> 3, cx = w & 7;
            const __nv_bfloat16* src;
            if      (tn == 0) src = Khp + (size_t)(kc0 + r) * 64 + cx * 8;
            else if (tn == 1) src = Klp + (size_t)(kc0 + r) * 64 + cx * 8;
            else if (tn == 2) src = Vhp + (size_t)(kc0 + r) * 64 + cx * 8;
            else              src = Vlp + (size_t)(kc0 + r) * 64 + cx * 8;
            cp16(base + (uint32_t)tn * 16384u + swz(r, cx), src);
        }
    }
    CP_COMMIT();            // G0
    issue_kv(1, 1);         // G1

    CP_WAIT1();             // G0 (Q + kv0) complete
    __syncthreads();

    // Q fragments (hi+lo) into registers
    uint32_t qh[4][4], ql[4][4];
    #pragma unroll
    for (int kf = 0; kf < 4; ++kf) {
        int row = wid * 16 + (lane & 15);
        int cx  = kf * 2 + (lane >> 4);
        uint32_t a = sb + swz(row, cx);
        ldsm4(qh[kf], a);
        ldsm4(ql[kf], a + 16384);
    }

    float o[8][4];
    #pragma unroll
    for (int i = 0; i < 8; ++i)
        #pragma unroll
        for (int j = 0; j < 4; ++j) o[i][j] = 0.f;
    float mrow[2] = {-1e30f, -1e30f};
    float lrow[2] = {0.f, 0.f};

    for (int t = 0; t < 16; ++t) {
        if (t == 15) { CP_WAIT0(); } else { CP_WAIT1(); }
        __syncthreads();
        if (t <= 13) issue_kv(t + 2, (t + 2) % 3);

        const uint32_t base = sb + 32768u + (uint32_t)(t % 3) * 65536u;

        // S = Q @ K^T
        float s[16][4];
        #pragma unroll
        for (int nfp = 0; nfp < 8; ++nfp) {
            float s0[4] = {0.f, 0.f, 0.f, 0.f};
            float s1[4] = {0.f, 0.f, 0.f, 0.f};
            #pragma unroll
            for (int kf = 0; kf < 4; ++kf) {
                int row = nfp * 16 + ((lane >> 4) << 3) + (lane & 7);
                int cx  = kf * 2 + ((lane >> 3) & 1);
                uint32_t a = base + swz(row, cx);
                uint32_t rh[4], rl[4];
                ldsm4(rh, a);
                ldsm4(rl, a + 16384);
                mma_bf16(s0, qh[kf], rh[0], rh[1]);
                mma_bf16(s0, qh[kf], rl[0], rl[1]);
                mma_bf16(s0, ql[kf], rh[0], rh[1]);
                mma_bf16(s1, qh[kf], rh[2], rh[3]);
                mma_bf16(s1, qh[kf], rl[2], rl[3]);
                mma_bf16(s1, ql[kf], rh[2], rh[3]);
            }
            #pragma unroll
            for (int e = 0; e < 4; ++e) { s[2*nfp][e] = s0[e]; s[2*nfp+1][e] = s1[e]; }
        }

        // online softmax (base-2; scale folded into Q)
        #pragma unroll
        for (int h = 0; h < 2; ++h) {
            float mx = -1e30f;
            #pragma unroll
            for (int nf = 0; nf < 16; ++nf)
                mx = fmaxf(mx, fmaxf(s[nf][2*h], s[nf][2*h + 1]));
            mx = fmaxf(mx, __shfl_xor_sync(0xffffffffu, mx, 1));
            mx = fmaxf(mx, __shfl_xor_sync(0xffffffffu, mx, 2));
            float mn = fmaxf(mrow[h], mx);
            float corr = ex2f(mrow[h] - mn);
            float rs = 0.f;
            #pragma unroll
            for (int nf = 0; nf < 16; ++nf) {
                float p0 = ex2f(s[nf][2*h]     - mn);
                float p1 = ex2f(s[nf][2*h + 1] - mn);
                s[nf][2*h] = p0; s[nf][2*h + 1] = p1;
                rs += p0 + p1;
            }
            rs += __shfl_xor_sync(0xffffffffu, rs, 1);
            rs += __shfl_xor_sync(0xffffffffu, rs, 2);
            lrow[h] = lrow[h] * corr + rs;
            mrow[h] = mn;
            #pragma unroll
            for (int nf = 0; nf < 8; ++nf) {
                o[nf][2*h] *= corr; o[nf][2*h + 1] *= corr;
            }
        }

        // O += P @ V  (P packed in-register per kf)
        #pragma unroll
        for (int kf = 0; kf < 8; ++kf) {
            uint32_t ah2[4], al2[4];
            #pragma unroll
            for (int e = 0; e < 2; ++e) {
                const float* sp = s[2*kf + e];
                __nv_bfloat162 h01 = __floats2bfloat162_rn(sp[0], sp[1]);
                __nv_bfloat162 h23 = __floats2bfloat162_rn(sp[2], sp[3]);
                float2 f01 = __bfloat1622float2(h01);
                float2 f23 = __bfloat1622float2(h23);
                __nv_bfloat162 l01 = __floats2bfloat162_rn(sp[0] - f01.x, sp[1] - f01.y);
                __nv_bfloat162 l23 = __floats2bfloat162_rn(sp[2] - f23.x, sp[3] - f23.y);
                ah2[2*e + 0] = *(uint32_t*)&h01; ah2[2*e + 1] = *(uint32_t*)&h23;
                al2[2*e + 0] = *(uint32_t*)&l01; al2[2*e + 1] = *(uint32_t*)&l23;
            }
            #pragma unroll
            for (int dn = 0; dn < 4; ++dn) {
                int row = kf * 16 + ((lane >> 3) & 1) * 8 + (lane & 7);
                int cx  = dn * 2 + (lane >> 4);
                uint32_t a = base + 32768 + swz(row, cx);
                uint32_t vh4[4], vl4[4];
                ldsm4t(vh4, a);
                ldsm4t(vl4, a + 16384);
                mma_bf16(o[2*dn],   ah2, vh4[0], vh4[1]);
                mma_bf16(o[2*dn],   ah2, vl4[0], vl4[1]);
                mma_bf16(o[2*dn],   al2, vh4[0], vh4[1]);
                mma_bf16(o[2*dn+1], ah2, vh4[2], vh4[3]);
                mma_bf16(o[2*dn+1], ah2, vl4[2], vl4[3]);
                mma_bf16(o[2*dn+1], al2, vh4[2], vh4[3]);
            }
        }
    }

    // epilogue: normalize, split, store [B,S,D]
    const int b  = bh >> 4;
    const int hh = bh & 15;
    #pragma unroll
    for (int h = 0; h < 2; ++h) {
        float inv = 1.0f / lrow[h];
        int srow = q0 + wid * 16 + (lane >> 2) + h * 8;
        #pragma unroll
        for (int nf = 0; nf < 8; ++nf) {
            int d = nf * 8 + (lane & 3) * 2;
            size_t off = ((size_t)b * SS + srow) * DD + hh * 64 + d;
            split2_store(o[nf][2*h] * inv, o[nf][2*h + 1] * inv,
                         g_s.AOh + off, g_s.AOl + off);
        }
    }
}

// ---------------------------------------------------------------------------
extern "C" void kernel_launch(void* const* d_in, const int* in_sizes, int n_in,
                              void* d_out, int out_size)
{
    const float* q  = (const float*)d_in[0];
    const float* k  = (const float*)d_in[1];
    const float* v  = (const float*)d_in[2];
    const float* Wq = (const float*)d_in[3];
    const float* bq = (const float*)d_in[4];
    const float* Wk = (const float*)d_in[5];
    const float* bk = (const float*)d_in[6];
    const float* Wv = (const float*)d_in[7];
    const float* bv = (const float*)d_in[8];
    const float* Wo = (const float*)d_in[9];
    const float* bo = (const float*)d_in[10];
    float* out = (float*)d_out;

    Scratch* S;
    cudaGetSymbolAddress((void**)&S, g_s);

    split_kernel<<<NIN/4/256, 256>>>((const float4*)q, S->aq_h, S->aq_l);
    split_kernel<<<NIN/4/256, 256>>>((const float4*)k, S->ak_h, S->ak_l);
    split_kernel<<<NIN/4/256, 256>>>((const float4*)v, S->av_h, S->av_l);
    split_kernel<<<NW/4/256, 256>>>((const float4*)Wq, S->wq_h, S->wq_l);
    split_kernel<<<NW/4/256, 256>>>((const float4*)Wk, S->wk_h, S->wk_l);
    split_kernel<<<NW/4/256, 256>>>((const float4*)Wv, S->wv_h, S->wv_l);
    split_kernel<<<NW/4/256, 256>>>((const float4*)Wo, S->wo_h, S->wo_l);

    cudaFuncSetAttribute(gemm_qkv, cudaFuncAttributeMaxDynamicSharedMemorySize, GEMM_SMEM);
    cudaFuncSetAttribute(gemm_o,   cudaFuncAttributeMaxDynamicSharedMemorySize, GEMM_SMEM);
    cudaFuncSetAttribute(flash_mma_kernel,
                         cudaFuncAttributeMaxDynamicSharedMemorySize, ATTN_SMEM);

    gemm_qkv<<<dim3(DD/256, MTOT/128, 3), 256, GEMM_SMEM>>>(bq, bk, bv);

    flash_mma_kernel<<<dim3(SS/128, BB*HH), 256, ATTN_SMEM>>>();

    gemm_o<<<dim3(DD/256, MTOT/128), 256, GEMM_SMEM>>>(bo, out);
}

// round 6
// speedup vs baseline: 3.6069x; 1.0213x over previous
#include <cuda_runtime.h>
#include <cuda_bf16.h>
#include <cstdint>
#include <stddef.h>

#define BB   2
#define SS   2048
#define DD   1024
#define HH   16
#define MTOT (BB*SS)            // 4096
#define NIN  ((size_t)MTOT*DD)  // 4194304
#define NW   ((size_t)DD*DD)    // 1048576

// ---------------------------------------------------------------------------
// Scratch: everything pre-split into bf16 hi/lo (static device alloc)
// ---------------------------------------------------------------------------
struct Scratch {
    __nv_bfloat16 aq_h[NIN], aq_l[NIN];
    __nv_bfloat16 ak_h[NIN], ak_l[NIN];
    __nv_bfloat16 av_h[NIN], av_l[NIN];
    __nv_bfloat16 wq_h[NW],  wq_l[NW];
    __nv_bfloat16 wk_h[NW],  wk_l[NW];
    __nv_bfloat16 wv_h[NW],  wv_l[NW];
    __nv_bfloat16 wo_h[NW],  wo_l[NW];
    __nv_bfloat16 Qh[NIN], Ql[NIN];       // [B,H,S,64], Q pre-scaled
    __nv_bfloat16 Kh[NIN], Kl[NIN];
    __nv_bfloat16 Vh[NIN], Vl[NIN];
    __nv_bfloat16 AOh[NIN], AOl[NIN];     // [B,S,D]
};
__device__ Scratch g_s;

// ---------------------------------------------------------------------------
// helpers
// ---------------------------------------------------------------------------
__device__ __forceinline__ uint32_t smem_u32(const void* p) {
    uint32_t a;
    asm("{ .reg .u64 t; cvta.to.shared.u64 t, %1; cvt.u32.u64 %0, t; }"
        : "=r"(a) : "l"(p));
    return a;
}
__device__ __forceinline__ void ldsm4(uint32_t* r, uint32_t a) {
    asm volatile("ldmatrix.sync.aligned.m8n8.x4.shared.b16 {%0,%1,%2,%3}, [%4];"
                 : "=r"(r[0]), "=r"(r[1]), "=r"(r[2]), "=r"(r[3]) : "r"(a));
}
__device__ __forceinline__ void ldsm4t(uint32_t* r, uint32_t a) {
    asm volatile("ldmatrix.sync.aligned.m8n8.x4.trans.shared.b16 {%0,%1,%2,%3}, [%4];"
                 : "=r"(r[0]), "=r"(r[1]), "=r"(r[2]), "=r"(r[3]) : "r"(a));
}
__device__ __forceinline__ void mma_bf16(float* c, const uint32_t* a,
                                         uint32_t b0, uint32_t b1) {
    asm volatile("mma.sync.aligned.m16n8k16.row.col.f32.bf16.bf16.f32 "
                 "{%0,%1,%2,%3}, {%4,%5,%6,%7}, {%8,%9}, {%0,%1,%2,%3};"
                 : "+f"(c[0]), "+f"(c[1]), "+f"(c[2]), "+f"(c[3])
                 : "r"(a[0]), "r"(a[1]), "r"(a[2]), "r"(a[3]), "r"(b0), "r"(b1));
}
__device__ __forceinline__ float ex2f(float x) {
    float y; asm("ex2.approx.f32 %0, %1;" : "=f"(y) : "f"(x)); return y;
}
__device__ __forceinline__ void cp16(uint32_t dst, const void* src) {
    asm volatile("cp.async.cg.shared.global [%0], [%1], 16;"
                 :: "r"(dst), "l"(src) : "memory");
}
#define CP_COMMIT() asm volatile("cp.async.commit_group;" ::: "memory")
#define CP_WAIT0()  asm volatile("cp.async.wait_group 0;" ::: "memory")
#define CP_WAIT1()  asm volatile("cp.async.wait_group 1;" ::: "memory")

// swizzled offset within a tile whose rows are 128B: row r, 16B-chunk cx
__device__ __forceinline__ uint32_t swz(int r, int cx) {
    return (uint32_t)(r * 128 + ((cx ^ (r & 7)) << 4));
}

__device__ __forceinline__ void split2_store(float x, float y,
                                             __nv_bfloat16* hp, __nv_bfloat16* lp) {
    __nv_bfloat162 H = __floats2bfloat162_rn(x, y);
    float2 F = __bfloat1622float2(H);
    __nv_bfloat162 L = __floats2bfloat162_rn(x - F.x, y - F.y);
    *(__nv_bfloat162*)hp = H;
    *(__nv_bfloat162*)lp = L;
}

// ---------------------------------------------------------------------------
// fused elementwise fp32 -> bf16 hi/lo splits (grid.z selects tensor)
// ---------------------------------------------------------------------------
__global__ void __launch_bounds__(256)
split_in_kernel(const float4* __restrict__ q, const float4* __restrict__ k,
                const float4* __restrict__ v)
{
    int z = blockIdx.z;
    const float4* src = (z == 0) ? q : (z == 1) ? k : v;
    __nv_bfloat16 *hi, *lo;
    if (z == 0)      { hi = g_s.aq_h; lo = g_s.aq_l; }
    else if (z == 1) { hi = g_s.ak_h; lo = g_s.ak_l; }
    else             { hi = g_s.av_h; lo = g_s.av_l; }
    size_t i = (size_t)blockIdx.x * blockDim.x + threadIdx.x;
    float4 val = src[i];
    split2_store(val.x, val.y, hi + 4*i,     lo + 4*i);
    split2_store(val.z, val.w, hi + 4*i + 2, lo + 4*i + 2);
}

__global__ void __launch_bounds__(256)
split_w_kernel(const float4* __restrict__ wq, const float4* __restrict__ wk,
               const float4* __restrict__ wv, const float4* __restrict__ wo)
{
    int z = blockIdx.z;
    const float4* src = (z == 0) ? wq : (z == 1) ? wk : (z == 2) ? wv : wo;
    __nv_bfloat16 *hi, *lo;
    if (z == 0)      { hi = g_s.wq_h; lo = g_s.wq_l; }
    else if (z == 1) { hi = g_s.wk_h; lo = g_s.wk_l; }
    else if (z == 2) { hi = g_s.wv_h; lo = g_s.wv_l; }
    else             { hi = g_s.wo_h; lo = g_s.wo_l; }
    size_t i = (size_t)blockIdx.x * blockDim.x + threadIdx.x;
    float4 val = src[i];
    split2_store(val.x, val.y, hi + 4*i,     lo + 4*i);
    split2_store(val.z, val.w, hi + 4*i + 2, lo + 4*i + 2);
}

// ---------------------------------------------------------------------------
// GEMM body: C[4096,1024] = A @ W^T + bias, bf16x3.
// CTA tile 128(M) x 256(N), BK=64, 8 warps (2m x 4n), warp tile 64x64.
// 2-stage cp.async. smem/stage: Ah 16K | Al 16K | Wh 32K | Wl 32K = 96K.
// ---------------------------------------------------------------------------
#define GEMM_SMEM (2*98304)

template<int OUT_SPLIT>
__device__ __noinline__ void gemm_body(
    const __nv_bfloat16* __restrict__ Ah, const __nv_bfloat16* __restrict__ Al,
    const __nv_bfloat16* __restrict__ Wh, const __nv_bfloat16* __restrict__ Wl,
    const float* __restrict__ bias, float* __restrict__ Cf,
    __nv_bfloat16* __restrict__ Ch, __nv_bfloat16* __restrict__ Cl,
    float oscale, char* smg)
{
    const uint32_t sb = smem_u32(smg);
    const int tid = threadIdx.x, lane = tid & 31, wid = tid >> 5;
    const int wm = wid >> 2, wn = wid & 3;
    const int m0 = blockIdx.y * 128, n0 = blockIdx.x * 256;

    auto issue = [&](int c, int stage) {
        const int k0 = c * 64;
        const uint32_t base = sb + (uint32_t)stage * 98304u;
        #pragma unroll
        for (int i = 0; i < 24; ++i) {
            int idx = tid + i * 256;          // 0..6143
            const __nv_bfloat16* src;
            uint32_t roff;
            int w;
            if (idx < 2048) {                 // A hi/lo: 128 rows each
                int tn = idx >> 10; w = idx & 1023;
                int r = w >> 3;
                src = (tn ? Al : Ah) + (size_t)(m0 + r) * DD + k0 + (w & 7) * 8;
                roff = (uint32_t)tn * 16384u;
            } else {                          // W hi/lo: 256 rows each
                int j = idx - 2048;
                int tn = j >> 11; w = j & 2047;
                int r = w >> 3;
                src = (tn ? Wl : Wh) + (size_t)(n0 + r) * DD + k0 + (w & 7) * 8;
                roff = 32768u + (uint32_t)tn * 32768u;
            }
            cp16(base + roff + swz(w >> 3, w & 7), src);
        }
        CP_COMMIT();
    };

    float acc[4][8][4];
    #pragma unroll
    for (int i = 0; i < 4; ++i)
        #pragma unroll
        for (int j = 0; j < 8; ++j)
            #pragma unroll
            for (int e = 0; e < 4; ++e) acc[i][j][e] = 0.f;

    issue(0, 0);
    for (int c = 0; c < 16; ++c) {
        if (c < 15) { issue(c + 1, (c + 1) & 1); CP_WAIT1(); }
        else        { CP_WAIT0(); }
        __syncthreads();

        const uint32_t base = sb + (uint32_t)(c & 1) * 98304u;
        #pragma unroll
        for (int ks = 0; ks < 4; ++ks) {
            uint32_t ahf[4][4], alf[4][4];
            #pragma unroll
            for (int mf = 0; mf < 4; ++mf) {
                int row = wm * 64 + mf * 16 + (lane & 15);
                int cx  = ks * 2 + (lane >> 4);
                uint32_t a = base + swz(row, cx);
                ldsm4(ahf[mf], a);
                ldsm4(alf[mf], a + 16384);
            }
            uint32_t bhf[8][2], blf[8][2];
            #pragma unroll
            for (int nfp = 0; nfp < 4; ++nfp) {
                int row = wn * 64 + nfp * 16 + ((lane >> 4) << 3) + (lane & 7);
                int cx  = ks * 2 + ((lane >> 3) & 1);
                uint32_t a = base + 32768 + swz(row, cx);
                uint32_t r[4];
                ldsm4(r, a);
                bhf[2*nfp][0] = r[0]; bhf[2*nfp][1] = r[1];
                bhf[2*nfp+1][0] = r[2]; bhf[2*nfp+1][1] = r[3];
                ldsm4(r, a + 32768);
                blf[2*nfp][0] = r[0]; blf[2*nfp][1] = r[1];
                blf[2*nfp+1][0] = r[2]; blf[2*nfp+1][1] = r[3];
            }
            #pragma unroll
            for (int mf = 0; mf < 4; ++mf)
                #pragma unroll
                for (int nf = 0; nf < 8; ++nf) {
                    mma_bf16(acc[mf][nf], ahf[mf], bhf[nf][0], bhf[nf][1]);
                    mma_bf16(acc[mf][nf], ahf[mf], blf[nf][0], blf[nf][1]);
                    mma_bf16(acc[mf][nf], alf[mf], bhf[nf][0], bhf[nf][1]);
                }
        }
        __syncthreads();
    }

    #pragma unroll
    for (int mf = 0; mf < 4; ++mf)
        #pragma unroll
        for (int nf = 0; nf < 8; ++nf)
            #pragma unroll
            for (int h = 0; h < 2; ++h) {
                int m = m0 + wm * 64 + mf * 16 + (lane >> 2) + h * 8;
                int n = n0 + wn * 64 + nf * 8 + (lane & 3) * 2;
                float2 bb = *(const float2*)(bias + n);
                float vx = acc[mf][nf][2*h + 0] + bb.x;
                float vy = acc[mf][nf][2*h + 1] + bb.y;
                if (OUT_SPLIT) {
                    vx *= oscale; vy *= oscale;
                    int b = m >> 11, s = m & (SS - 1);
                    int hh = n >> 6, d = n & 63;
                    size_t off = ((((size_t)b * HH + hh) * SS + s) << 6) + d;
                    split2_store(vx, vy, Ch + off, Cl + off);
                } else {
                    float2 val; val.x = vx; val.y = vy;
                    *(float2*)(Cf + (size_t)m * DD + n) = val;
                }
            }
}

// fused Q/K/V projections: blockIdx.z selects the GEMM
__global__ void __launch_bounds__(256, 1)
gemm_qkv(const float* __restrict__ bq, const float* __restrict__ bk,
         const float* __restrict__ bv)
{
    extern __shared__ char smg[];
    const float QSCALE = 0.125f * 1.44269504088896340736f;
    int z = blockIdx.z;
    if (z == 0)
        gemm_body<1>(g_s.aq_h, g_s.aq_l, g_s.wq_h, g_s.wq_l, bq,
                     nullptr, g_s.Qh, g_s.Ql, QSCALE, smg);
    else if (z == 1)
        gemm_body<1>(g_s.ak_h, g_s.ak_l, g_s.wk_h, g_s.wk_l, bk,
                     nullptr, g_s.Kh, g_s.Kl, 1.0f, smg);
    else
        gemm_body<1>(g_s.av_h, g_s.av_l, g_s.wv_h, g_s.wv_l, bv,
                     nullptr, g_s.Vh, g_s.Vl, 1.0f, smg);
}

__global__ void __launch_bounds__(256, 1)
gemm_o(const float* __restrict__ bo, float* __restrict__ out)
{
    extern __shared__ char smg[];
    gemm_body<0>(g_s.AOh, g_s.AOl, g_s.wo_h, g_s.wo_l, bo,
                 out, nullptr, nullptr, 1.0f, smg);
}

// ---------------------------------------------------------------------------
// Flash attention, bf16x3, 3-stage cp.async, softmax hidden under MMA by
// kc-sub-tile interleave: [QK all] [sm sub0] [PV sub0] [sm sub1] [PV sub1].
// grid (16, 32), 256 threads. q-tile 128, kc-tile 128 (2 x 64 sub), dk 64.
// smem: Qh/Ql 32KB + 3 stages x {Kh,Kl,Vh,Vl} 64KB = 229376 B.
// ---------------------------------------------------------------------------
#define ATTN_SMEM (32768 + 3*65536)

__global__ void __launch_bounds__(256, 1)
flash_mma_kernel()
{
    extern __shared__ char smf[];
    const uint32_t sb = smem_u32(smf);
    const int tid = threadIdx.x, lane = tid & 31, wid = tid >> 5;
    const int bh = blockIdx.y;
    const int q0 = blockIdx.x * 128;
    const size_t hbase = (size_t)bh * SS * 64;

    const __nv_bfloat16* Qhp = g_s.Qh + hbase;
    const __nv_bfloat16* Qlp = g_s.Ql + hbase;
    const __nv_bfloat16* Khp = g_s.Kh + hbase;
    const __nv_bfloat16* Klp = g_s.Kl + hbase;
    const __nv_bfloat16* Vhp = g_s.Vh + hbase;
    const __nv_bfloat16* Vlp = g_s.Vl + hbase;

    auto issue_kv = [&](int t, int stage) {
        const int kc0 = t * 128;
        const uint32_t base = sb + 32768u + (uint32_t)stage * 65536u;
        #pragma unroll
        for (int i = 0; i < 16; ++i) {
            int idx = tid + i * 256;      // 0..4095
            int tn  = idx >> 10;          // 0:Kh 1:Kl 2:Vh 3:Vl
            int w   = idx & 1023;
            int r   = w >> 3, cx = w & 7;
            const __nv_bfloat16* src;
            if      (tn == 0) src = Khp + (size_t)(kc0 + r) * 64 + cx * 8;
            else if (tn == 1) src = Klp + (size_t)(kc0 + r) * 64 + cx * 8;
            else if (tn == 2) src = Vhp + (size_t)(kc0 + r) * 64 + cx * 8;
            else              src = Vlp + (size_t)(kc0 + r) * 64 + cx * 8;
            cp16(base + (uint32_t)tn * 16384u + swz(r, cx), src);
        }
        CP_COMMIT();
    };

    // G0 = Q + kv0, G1 = kv1
    #pragma unroll
    for (int i = 0; i < 8; ++i) {
        int idx = tid + i * 256;          // 0..2047
        int tn  = idx >> 10;              // 0:Qh 1:Ql
        int w   = idx & 1023;
        int r   = w >> 3, cx = w & 7;
        const __nv_bfloat16* src = (tn ? Qlp : Qhp) + (size_t)(q0 + r) * 64 + cx * 8;
        cp16(sb + (uint32_t)tn * 16384u + swz(r, cx), src);
    }
    {
        const uint32_t base = sb + 32768u;
        #pragma unroll
        for (int i = 0; i < 16; ++i) {
            int idx = tid + i * 256;
            int tn  = idx >> 10;
            int w   = idx & 1023;
            int r   = w >> 3, cx = w & 7;
            const __nv_bfloat16* src;
            if      (tn == 0) src = Khp + (size_t)r * 64 + cx * 8;
            else if (tn == 1) src = Klp + (size_t)r * 64 + cx * 8;
            else if (tn == 2) src = Vhp + (size_t)r * 64 + cx * 8;
            else              src = Vlp + (size_t)r * 64 + cx * 8;
            cp16(base + (uint32_t)tn * 16384u + swz(r, cx), src);
        }
    }
    CP_COMMIT();            // G0
    issue_kv(1, 1);         // G1

    CP_WAIT1();             // G0 (Q + kv0) complete
    __syncthreads();

    // Q fragments (hi+lo) into registers
    uint32_t qh[4][4], ql[4][4];
    #pragma unroll
    for (int kf = 0; kf < 4; ++kf) {
        int row = wid * 16 + (lane & 15);
        int cx  = kf * 2 + (lane >> 4);
        uint32_t a = sb + swz(row, cx);
        ldsm4(qh[kf], a);
        ldsm4(ql[kf], a + 16384);
    }

    float o[8][4];
    #pragma unroll
    for (int i = 0; i < 8; ++i)
        #pragma unroll
        for (int j = 0; j < 4; ++j) o[i][j] = 0.f;
    float mrow[2] = {-1e30f, -1e30f};
    float lrow[2] = {0.f, 0.f};

    for (int t = 0; t < 16; ++t) {
        if (t == 15) { CP_WAIT0(); } else { CP_WAIT1(); }
        __syncthreads();
        if (t <= 13) issue_kv(t + 2, (t + 2) % 3);

        const uint32_t base = sb + 32768u + (uint32_t)(t % 3) * 65536u;

        // ---- S = Q @ K^T for the FULL 128-kc tile (keeps tensor pipe fed
        //      through softmax of sub0) ----
        float s[16][4];
        #pragma unroll
        for (int nfp = 0; nfp < 8; ++nfp) {
            float s0[4] = {0.f, 0.f, 0.f, 0.f};
            float s1[4] = {0.f, 0.f, 0.f, 0.f};
            #pragma unroll
            for (int kf = 0; kf < 4; ++kf) {
                int row = nfp * 16 + ((lane >> 4) << 3) + (lane & 7);
                int cx  = kf * 2 + ((lane >> 3) & 1);
                uint32_t a = base + swz(row, cx);
                uint32_t rh[4], rl[4];
                ldsm4(rh, a);
                ldsm4(rl, a + 16384);
                mma_bf16(s0, qh[kf], rh[0], rh[1]);
                mma_bf16(s0, qh[kf], rl[0], rl[1]);
                mma_bf16(s0, ql[kf], rh[0], rh[1]);
                mma_bf16(s1, qh[kf], rh[2], rh[3]);
                mma_bf16(s1, qh[kf], rl[2], rl[3]);
                mma_bf16(s1, ql[kf], rh[2], rh[3]);
            }
            #pragma unroll
            for (int e = 0; e < 4; ++e) { s[2*nfp][e] = s0[e]; s[2*nfp+1][e] = s1[e]; }
        }

        // ---- two kc-64 sub-tiles: softmax(sub) then PV(sub); softmax of
        //      sub0 overlaps QK drain, softmax of sub1 overlaps PV(sub0) ----
        #pragma unroll
        for (int sub = 0; sub < 2; ++sub) {
            const int nf0 = sub * 8;   // s-frags [nf0, nf0+8)
            const int kf0 = sub * 4;   // V row-frags [kf0, kf0+4)

            // online softmax update over this sub-tile (base-2 domain)
            #pragma unroll
            for (int h = 0; h < 2; ++h) {
                float mx = -1e30f;
                #pragma unroll
                for (int nf = nf0; nf < nf0 + 8; ++nf)
                    mx = fmaxf(mx, fmaxf(s[nf][2*h], s[nf][2*h + 1]));
                mx = fmaxf(mx, __shfl_xor_sync(0xffffffffu, mx, 1));
                mx = fmaxf(mx, __shfl_xor_sync(0xffffffffu, mx, 2));
                float mn = fmaxf(mrow[h], mx);
                float corr = ex2f(mrow[h] - mn);
                float rs = 0.f;
                #pragma unroll
                for (int nf = nf0; nf < nf0 + 8; ++nf) {
                    float p0 = ex2f(s[nf][2*h]     - mn);
                    float p1 = ex2f(s[nf][2*h + 1] - mn);
                    s[nf][2*h] = p0; s[nf][2*h + 1] = p1;
                    rs += p0 + p1;
                }
                rs += __shfl_xor_sync(0xffffffffu, rs, 1);
                rs += __shfl_xor_sync(0xffffffffu, rs, 2);
                lrow[h] = lrow[h] * corr + rs;
                mrow[h] = mn;
                #pragma unroll
                for (int nf = 0; nf < 8; ++nf) {
                    o[nf][2*h] *= corr; o[nf][2*h + 1] *= corr;
                }
            }

            // O += P(sub) @ V(sub)  (P packed in-register per kf)
            #pragma unroll
            for (int kf = kf0; kf < kf0 + 4; ++kf) {
                uint32_t ah2[4], al2[4];
                #pragma unroll
                for (int e = 0; e < 2; ++e) {
                    const float* sp = s[2*kf + e];
                    __nv_bfloat162 h01 = __floats2bfloat162_rn(sp[0], sp[1]);
                    __nv_bfloat162 h23 = __floats2bfloat162_rn(sp[2], sp[3]);
                    float2 f01 = __bfloat1622float2(h01);
                    float2 f23 = __bfloat1622float2(h23);
                    __nv_bfloat162 l01 = __floats2bfloat162_rn(sp[0] - f01.x, sp[1] - f01.y);
                    __nv_bfloat162 l23 = __floats2bfloat162_rn(sp[2] - f23.x, sp[3] - f23.y);
                    ah2[2*e + 0] = *(uint32_t*)&h01; ah2[2*e + 1] = *(uint32_t*)&h23;
                    al2[2*e + 0] = *(uint32_t*)&l01; al2[2*e + 1] = *(uint32_t*)&l23;
                }
                #pragma unroll
                for (int dn = 0; dn < 4; ++dn) {
                    int row = kf * 16 + ((lane >> 3) & 1) * 8 + (lane & 7);
                    int cx  = dn * 2 + (lane >> 4);
                    uint32_t a = base + 32768 + swz(row, cx);
                    uint32_t vh4[4], vl4[4];
                    ldsm4t(vh4, a);
                    ldsm4t(vl4, a + 16384);
                    mma_bf16(o[2*dn],   ah2, vh4[0], vh4[1]);
                    mma_bf16(o[2*dn],   ah2, vl4[0], vl4[1]);
                    mma_bf16(o[2*dn],   al2, vh4[0], vh4[1]);
                    mma_bf16(o[2*dn+1], ah2, vh4[2], vh4[3]);
                    mma_bf16(o[2*dn+1], ah2, vl4[2], vl4[3]);
                    mma_bf16(o[2*dn+1], al2, vh4[2], vh4[3]);
                }
            }
        }
    }

    // epilogue: normalize, split, store [B,S,D]
    const int b  = bh >> 4;
    const int hh = bh & 15;
    #pragma unroll
    for (int h = 0; h < 2; ++h) {
        float inv = 1.0f / lrow[h];
        int srow = q0 + wid * 16 + (lane >> 2) + h * 8;
        #pragma unroll
        for (int nf = 0; nf < 8; ++nf) {
            int d = nf * 8 + (lane & 3) * 2;
            size_t off = ((size_t)b * SS + srow) * DD + hh * 64 + d;
            split2_store(o[nf][2*h] * inv, o[nf][2*h + 1] * inv,
                         g_s.AOh + off, g_s.AOl + off);
        }
    }
}

// ---------------------------------------------------------------------------
extern "C" void kernel_launch(void* const* d_in, const int* in_sizes, int n_in,
                              void* d_out, int out_size)
{
    const float* q  = (const float*)d_in[0];
    const float* k  = (const float*)d_in[1];
    const float* v  = (const float*)d_in[2];
    const float* Wq = (const float*)d_in[3];
    const float* bq = (const float*)d_in[4];
    const float* Wk = (const float*)d_in[5];
    const float* bk = (const float*)d_in[6];
    const float* Wv = (const float*)d_in[7];
    const float* bv = (const float*)d_in[8];
    const float* Wo = (const float*)d_in[9];
    const float* bo = (const float*)d_in[10];
    float* out = (float*)d_out;

    cudaFuncSetAttribute(gemm_qkv, cudaFuncAttributeMaxDynamicSharedMemorySize, GEMM_SMEM);
    cudaFuncSetAttribute(gemm_o,   cudaFuncAttributeMaxDynamicSharedMemorySize, GEMM_SMEM);
    cudaFuncSetAttribute(flash_mma_kernel,
                         cudaFuncAttributeMaxDynamicSharedMemorySize, ATTN_SMEM);

    // 5 launches per call, flash at position 4
    split_in_kernel<<<dim3(NIN/4/256, 1, 3), 256>>>(
        (const float4*)q, (const float4*)k, (const float4*)v);
    split_w_kernel<<<dim3(NW/4/256, 1, 4), 256>>>(
        (const float4*)Wq, (const float4*)Wk, (const float4*)Wv, (const float4*)Wo);

    gemm_qkv<<<dim3(DD/256, MTOT/128, 3), 256, GEMM_SMEM>>>(bq, bk, bv);

    flash_mma_kernel<<<dim3(SS/128, BB*HH), 256, ATTN_SMEM>>>();

    gemm_o<<<dim3(DD/256, MTOT/128), 256, GEMM_SMEM>>>(bo, out);
}